// round 1
// baseline (speedup 1.0000x reference)
#include <cuda_runtime.h>
#include <math.h>

#define Bn 8
#define Cc 96
#define Hh 128
#define Wd 128
#define HW (Hh*Wd)
#define NPB (Cc*HW)            /* 1,572,864 per-sample */
#define NELEM (Bn*NPB)         /* 12,582,912 */
#define TOTF 1572864.0f
#define EPSLN 1e-5f

/* ---------------- scratch (device globals; no allocation) ---------------- */
__device__ float4 g_bA1[NELEM/4];   /* x1 out of relu-split  */
__device__ float4 g_bA2[NELEM/4];   /* x2 out of relu-split  */
__device__ float4 g_bXR[NELEM/4];   /* residual xr           */
__device__ float4 g_bK1[NELEM/4];   /* conv(A1, aw1)         */
__device__ float4 g_bQ1[NELEM/4];   /* conv(A2, aw2)         */
__device__ float4 g_bV [NELEM/4];   /* conv(A1, aw3)         */
__device__ float4 g_bW2[NELEM/4];   /* conv(A2, w_conv2)     */
__device__ float4 g_bAO[NELEM/4];   /* attention conv output */
__device__ float  g_ATTN[Bn*Cc*Cc*9];
__device__ float  g_part[4*8*64*4]; /* [slot][b][block][comp] */
__device__ float  g_red [4*8*4];    /* [slot][b][comp]        */
__device__ float  g_coef[8*8];

/* ---------------- helpers ---------------- */
__device__ __forceinline__ float warp_sum(float v){
  #pragma unroll
  for (int o=16;o;o>>=1) v += __shfl_xor_sync(0xffffffffu, v, o);
  return v;
}

/* ---------------- reductions (deterministic: partials + ordered combine) -- */
__global__ void k_reduce_ss(const float* __restrict__ in, int slot)
{
  __shared__ float sm[2][8];
  int b = blockIdx.y;
  const float4* p = (const float4*)in + (size_t)b*(NPB/4);
  float s=0.f, ss=0.f;
  for (int i = blockIdx.x*blockDim.x + threadIdx.x; i < NPB/4; i += gridDim.x*blockDim.x){
    float4 v = p[i];
    s  += (v.x+v.y)+(v.z+v.w);
    ss += v.x*v.x + v.y*v.y + v.z*v.z + v.w*v.w;
  }
  s = warp_sum(s); ss = warp_sum(ss);
  int lane = threadIdx.x&31, w = threadIdx.x>>5;
  if (lane==0){ sm[0][w]=s; sm[1][w]=ss; }
  __syncthreads();
  if (threadIdx.x==0){
    float a=0.f,c=0.f;
    for (int i=0;i<8;i++){ a+=sm[0][i]; c+=sm[1][i]; }
    float* o = &g_part[((slot*8+b)*64 + blockIdx.x)*4];
    o[0]=a; o[1]=c;
  }
}

__global__ void k_reduce_pos(const float* __restrict__ in)
{
  __shared__ float sm[3][8];
  int b = blockIdx.y;
  float m = g_red[(0*8+b)*4+0] * (1.0f/TOTF);
  const float4* p = (const float4*)in + (size_t)b*(NPB/4);
  float P=0.f, PP=0.f, cnt=0.f;
  for (int i = blockIdx.x*blockDim.x + threadIdx.x; i < NPB/4; i += gridDim.x*blockDim.x){
    float4 v = p[i];
    float a;
    a=v.x-m; if(a>0.f){P+=a;PP+=a*a;cnt+=1.f;}
    a=v.y-m; if(a>0.f){P+=a;PP+=a*a;cnt+=1.f;}
    a=v.z-m; if(a>0.f){P+=a;PP+=a*a;cnt+=1.f;}
    a=v.w-m; if(a>0.f){P+=a;PP+=a*a;cnt+=1.f;}
  }
  P = warp_sum(P); PP = warp_sum(PP); cnt = warp_sum(cnt);
  int lane = threadIdx.x&31, w = threadIdx.x>>5;
  if (lane==0){ sm[0][w]=P; sm[1][w]=PP; sm[2][w]=cnt; }
  __syncthreads();
  if (threadIdx.x==0){
    float a=0.f,c=0.f,d=0.f;
    for (int i=0;i<8;i++){ a+=sm[0][i]; c+=sm[1][i]; d+=sm[2][i]; }
    float* o = &g_part[((1*8+b)*64 + blockIdx.x)*4];
    o[0]=a; o[1]=c; o[2]=d;
  }
}

__global__ void k_combine(int slot)
{
  int t = threadIdx.x;
  if (t < 32){
    int b = t>>2, c = t&3;
    float s=0.f;
    const float* p = &g_part[((slot*8+b)*64)*4 + c];
    for (int i=0;i<64;i++) s += p[i*4];
    g_red[(slot*8+b)*4 + c] = s;
  }
}

/* ---------------- closed-form relu-split-norm coefficients ---------------- */
__global__ void k_coef()
{
  int b = threadIdx.x;
  if (b >= 8) return;
  float S  = g_red[(0*8+b)*4+0], SS = g_red[(0*8+b)*4+1];
  float P  = g_red[(1*8+b)*4+0], PP = g_red[(1*8+b)*4+1], np = g_red[(1*8+b)*4+2];
  float T = TOTF;
  float m = S/T;
  float neg = T - np;
  float avg1 = P/np;
  float mean1 = (P + avg1*neg)/T;
  float var1  = (PP + avg1*avg1*neg)/T - mean1*mean1;
  float inv1  = 1.0f/sqrtf(var1 + EPSLN);
  float s1    = sqrtf(np/T);
  float SSc = SS - S*S/T;
  float QQ  = SSc - PP;
  float avg2  = -P/neg;
  float mean2 = (-P + avg2*np)/T;
  float var2  = (QQ + avg2*avg2*np)/T - mean2*mean2;
  float inv2  = 1.0f/sqrtf(var2 + EPSLN);
  float s2    = sqrtf(neg/T);
  float* c = &g_coef[b*8];
  c[0]=m; c[1]=mean1; c[2]=s1*inv1; c[3]=s1*(avg1-mean1)*inv1;
  c[4]=mean2; c[5]=s2*inv2; c[6]=s2*(avg2-mean2)*inv2;
}

/* ---------------- elementwise: produce A1, A2, XR ---------------- */
__global__ void k_elemwise(const float4* __restrict__ x,
    const float* __restrict__ sc1p, const float* __restrict__ sc2p,
    const float* __restrict__ rcp,  const float* __restrict__ nc1p,
    const float* __restrict__ nc2p,
    float4* __restrict__ A1, float4* __restrict__ A2, float4* __restrict__ XR)
{
  int idx = blockIdx.x*blockDim.x + threadIdx.x;
  if (idx >= NELEM/4) return;
  int b = idx / (NPB/4);
  const float* cf = &g_coef[b*8];
  float m=cf[0], mean1=cf[1], g1=cf[2], c1n=cf[3], mean2=cf[4], g2=cf[5], c2n=cf[6];
  float sc1=sc1p[0], sc2=sc2p[0], rc=rcp[0], nc1=nc1p[0], nc2=nc2p[0];
  float4 xv = x[idx];
  float xi[4] = {xv.x, xv.y, xv.z, xv.w};
  float o1[4], o2[4], o3[4];
  #pragma unroll
  for (int k=0;k<4;k++){
    float xc = xi[k]-m;
    float x1n, x2n, v1, v2;
    if (xc > 0.f){ x1n=(xc-mean1)*g1; x2n=c2n; v1=sc1*xc+x1n; v2=x2n; }
    else         { x1n=c1n; x2n=(xc-mean2)*g2; v1=x1n; v2=sc2*xc+x2n; }
    o1[k]=v1; o2[k]=v2; o3[k]=0.5f*(nc1*x1n+nc2*x2n)+rc*xc;
  }
  A1[idx]=make_float4(o1[0],o1[1],o1[2],o1[3]);
  A2[idx]=make_float4(o2[0],o2[1],o2[2],o2[3]);
  XR[idx]=make_float4(o3[0],o3[1],o3[2],o3[3]);
}

/* ---------------- direct 3x3 conv, 96->96, NCHW ----------------
   block: 256 thr; tile 32x32 spatial, 16 output chans; 4 px/thread.
   per_batch!=0 -> weights are [B][96][96][3][3] (attention conv).    */
__global__ void __launch_bounds__(256, 2)
k_conv3x3(const float* __restrict__ in, const float* __restrict__ w,
          float* __restrict__ out, int per_batch)
{
  __shared__ float s_in[8][34*35];   /* stride 35: conflict-free reads */
  __shared__ float s_w[16*8*9];
  const int b = blockIdx.z;
  const int oc0 = blockIdx.y * 16;
  const int tileY = (blockIdx.x >> 2) * 32;
  const int tileX = (blockIdx.x & 3) * 32;
  const int tid = threadIdx.x;
  const int r  = tid >> 3;
  const int x0 = (tid & 7) * 4;
  const float* wb = w + (per_batch ? (size_t)b*Cc*Cc*9 : 0);

  float acc[16][4];
  #pragma unroll
  for (int o=0;o<16;o++){
    #pragma unroll
    for (int p=0;p<4;p++) acc[o][p]=0.f;
  }

  for (int ic0 = 0; ic0 < Cc; ic0 += 8){
    for (int idx = tid; idx < 8*34*34; idx += 256){
      int ic  = idx / 1156;
      int rem = idx - ic*1156;
      int iy  = rem / 34, ix = rem - iy*34;
      int gy = tileY + iy - 1, gx = tileX + ix - 1;
      float v = 0.f;
      if ((unsigned)gy < 128u && (unsigned)gx < 128u)
        v = in[(((size_t)b*Cc + ic0+ic)*Hh + gy)*Wd + gx];
      s_in[ic][iy*35+ix] = v;
    }
    for (int idx = tid; idx < 1152; idx += 256){
      int oc = idx / 72; int rem = idx - oc*72;
      s_w[idx] = wb[((size_t)(oc0+oc)*Cc + ic0)*9 + rem];
    }
    __syncthreads();
    #pragma unroll
    for (int ic=0; ic<8; ic++){
      float iv[3][6];
      #pragma unroll
      for (int dr=0; dr<3; dr++){
        #pragma unroll
        for (int dc=0; dc<6; dc++)
          iv[dr][dc] = s_in[ic][(r+dr)*35 + x0 + dc];
      }
      #pragma unroll
      for (int oc=0; oc<16; oc++){
        float wv[9];
        #pragma unroll
        for (int k=0;k<9;k++) wv[k] = s_w[oc*72 + ic*9 + k];
        #pragma unroll
        for (int p=0;p<4;p++){
          float a = acc[oc][p];
          #pragma unroll
          for (int dr=0;dr<3;dr++){
            #pragma unroll
            for (int dc=0;dc<3;dc++)
              a += iv[dr][p+dc]*wv[dr*3+dc];
          }
          acc[oc][p]=a;
        }
      }
    }
    __syncthreads();
  }
  #pragma unroll
  for (int oc=0;oc<16;oc++){
    float4 v = make_float4(acc[oc][0],acc[oc][1],acc[oc][2],acc[oc][3]);
    *(float4*)(out + ((((size_t)b*Cc + oc0+oc)*Hh + tileY + r)*Wd + tileX + x0)) = v;
  }
}

/* ---------------- attention GEMM: attn[b,q,c,k] = sum_l K[c,pix]Q[q,pix] --- */
__global__ void k_attn_gemm(const float* __restrict__ K1, const float* __restrict__ Q1,
                            float* __restrict__ attn)
{
  __shared__ float sk[16][96];
  __shared__ float sq[16][96];
  const int kidx = blockIdx.x;          /* 0..8 */
  const int kh = kidx/3, kw = kidx%3;
  const int b = blockIdx.y;
  const int tid = threadIdx.x;
  const int q0 = (tid >> 4) * 6;
  const int c0 = (tid & 15) * 6;
  float acc[6][6];
  #pragma unroll
  for (int i=0;i<6;i++){
    #pragma unroll
    for (int j=0;j<6;j++) acc[i][j]=0.f;
  }

  for (int l0 = 0; l0 < 1764; l0 += 16){
    for (int idx = tid; idx < 1536; idx += 256){
      int c = idx >> 4; int ll = idx & 15;
      int l = l0 + ll;
      float kv=0.f, qv=0.f;
      if (l < 1764){
        int ho = l/42, wo = l - ho*42;
        int pix = (3*ho+kh)*Wd + (3*wo+kw);
        size_t off = ((size_t)b*Cc + c)*HW + pix;
        kv = K1[off]; qv = Q1[off];
      }
      sk[ll][c]=kv; sq[ll][c]=qv;
    }
    __syncthreads();
    #pragma unroll
    for (int ll=0; ll<16; ll++){
      float qv[6], cv[6];
      #pragma unroll
      for (int i=0;i<6;i++) qv[i]=sq[ll][q0+i];
      #pragma unroll
      for (int j=0;j<6;j++) cv[j]=sk[ll][c0+j];
      #pragma unroll
      for (int i=0;i<6;i++){
        #pragma unroll
        for (int j=0;j<6;j++) acc[i][j] += qv[i]*cv[j];
      }
    }
    __syncthreads();
  }
  #pragma unroll
  for (int i=0;i<6;i++){
    #pragma unroll
    for (int j=0;j<6;j++)
      attn[((size_t)b*Cc + q0+i)*864 + (size_t)(c0+j)*9 + kidx] = acc[i][j];
  }
}

/* ---------------- softmax over 864, scaled by 1/sqrt(864) ---------------- */
__global__ void k_softmax(float* __restrict__ attn)
{
  __shared__ float sm[8];
  __shared__ float bc;
  const int b = blockIdx.y, q = blockIdx.x, tid = threadIdx.x;
  float* row = attn + ((size_t)(b*Cc+q))*864;
  const float scale = 0.034020690871988586f;   /* 1/sqrt(864) */
  float mx = -1e30f;
  for (int i=tid;i<864;i+=256) mx = fmaxf(mx, row[i]*scale);
  #pragma unroll
  for (int o=16;o;o>>=1) mx = fmaxf(mx, __shfl_xor_sync(0xffffffffu, mx, o));
  if ((tid&31)==0) sm[tid>>5]=mx;
  __syncthreads();
  if (tid==0){ float v=sm[0]; for(int i=1;i<8;i++) v=fmaxf(v,sm[i]); bc=v; }
  __syncthreads();
  mx = bc;
  float s=0.f;
  for (int i=tid;i<864;i+=256){ float e = expf(row[i]*scale - mx); row[i]=e; s+=e; }
  s = warp_sum(s);
  __syncthreads();
  if ((tid&31)==0) sm[tid>>5]=s;
  __syncthreads();
  if (tid==0){ float v=0.f; for(int i=0;i<8;i++) v+=sm[i]; bc=1.0f/v; }
  __syncthreads();
  float inv = bc;
  for (int i=tid;i<864;i+=256) row[i]*=inv;
}

/* ---------------- final: LN(AO), LN(W2)*A1, 1x1 conv 192->96, +XR +bias --- */
__global__ void __launch_bounds__(256)
k_final(const float* __restrict__ wf, const float* __restrict__ bias,
        const float* __restrict__ AO, const float* __restrict__ W2,
        const float* __restrict__ A1, const float* __restrict__ XR,
        float* __restrict__ out)
{
  __shared__ float yv[48][128];
  __shared__ float ws[96][48];
  const int b = blockIdx.y;
  const int pix0 = blockIdx.x * 128;
  const int tid = threadIdx.x;
  const int g = tid >> 6;     /* 0..3 : 24 out-chans each */
  const int s = tid & 63;     /* pixels s and s+64        */

  float S1 = g_red[(2*8+b)*4+0], SS1 = g_red[(2*8+b)*4+1];
  float m1 = S1*(1.0f/TOTF);
  float inv1 = 1.0f/sqrtf(SS1*(1.0f/TOTF) - m1*m1 + EPSLN);
  float S2 = g_red[(3*8+b)*4+0], SS2 = g_red[(3*8+b)*4+1];
  float m2 = S2*(1.0f/TOTF);
  float inv2 = 1.0f/sqrtf(SS2*(1.0f/TOTF) - m2*m2 + EPSLN);

  float acc0[24], acc1[24];
  #pragma unroll
  for (int j=0;j<24;j++){ acc0[j]=0.f; acc1[j]=0.f; }

  for (int i0=0; i0<192; i0+=48){
    for (int idx=tid; idx<48*128; idx+=256){
      int ii = idx >> 7; int p = idx & 127;
      int i = i0+ii;
      float v;
      if (i < 96){
        v = (AO[((size_t)b*Cc+i)*HW + pix0+p]-m1)*inv1;
      } else {
        size_t o = ((size_t)b*Cc+(i-96))*HW + pix0+p;
        v = (W2[o]-m2)*inv2*A1[o];
      }
      yv[ii][p] = v;
    }
    for (int idx=tid; idx<96*48; idx+=256){
      int o = idx/48, ii = idx-o*48;
      ws[o][ii] = wf[(size_t)o*192 + i0+ii];
    }
    __syncthreads();
    #pragma unroll 4
    for (int ii=0; ii<48; ii++){
      float v0 = yv[ii][s], v1 = yv[ii][s+64];
      #pragma unroll
      for (int j=0;j<24;j++){
        float w = ws[g*24+j][ii];
        acc0[j] += w*v0; acc1[j] += w*v1;
      }
    }
    __syncthreads();
  }
  #pragma unroll
  for (int j=0;j<24;j++){
    int o = g*24+j;
    size_t off = ((size_t)b*Cc+o)*HW + pix0;
    float bb = bias[o];
    out[off+s]    = XR[off+s]    + bb + acc0[j];
    out[off+s+64] = XR[off+s+64] + bb + acc1[j];
  }
}

/* ---------------- host ---------------- */
extern "C" void kernel_launch(void* const* d_in, const int* in_sizes, int n_in,
                              void* d_out, int out_size)
{
  const float* x    = (const float*)d_in[0];
  const float* wc2  = (const float*)d_in[1];
  const float* aw1  = (const float*)d_in[2];
  const float* aw2  = (const float*)d_in[3];
  const float* aw3  = (const float*)d_in[4];
  const float* wf   = (const float*)d_in[5];
  const float* bf   = (const float*)d_in[6];
  const float* sc1  = (const float*)d_in[7];
  const float* sc2  = (const float*)d_in[8];
  const float* rc   = (const float*)d_in[9];
  const float* nc1  = (const float*)d_in[10];
  const float* nc2  = (const float*)d_in[11];

  float *pA1,*pA2,*pXR,*pK1,*pQ1,*pV,*pW2,*pAO,*pATTN;
  cudaGetSymbolAddress((void**)&pA1, g_bA1);
  cudaGetSymbolAddress((void**)&pA2, g_bA2);
  cudaGetSymbolAddress((void**)&pXR, g_bXR);
  cudaGetSymbolAddress((void**)&pK1, g_bK1);
  cudaGetSymbolAddress((void**)&pQ1, g_bQ1);
  cudaGetSymbolAddress((void**)&pV , g_bV );
  cudaGetSymbolAddress((void**)&pW2, g_bW2);
  cudaGetSymbolAddress((void**)&pAO, g_bAO);
  cudaGetSymbolAddress((void**)&pATTN, g_ATTN);

  /* stats of x (deterministic two-stage) */
  k_reduce_ss <<<dim3(64,8),256>>>(x, 0);
  k_combine   <<<1,32>>>(0);
  k_reduce_pos<<<dim3(64,8),256>>>(x);
  k_combine   <<<1,32>>>(1);
  k_coef      <<<1,8>>>();

  /* relu-split-norm elementwise */
  k_elemwise<<<NELEM/4/256,256>>>((const float4*)x, sc1,sc2,rc,nc1,nc2,
                                  (float4*)pA1,(float4*)pA2,(float4*)pXR);

  /* four fixed-weight 3x3 convs */
  k_conv3x3<<<dim3(16,6,8),256>>>(pA1, aw1, pK1, 0);
  k_conv3x3<<<dim3(16,6,8),256>>>(pA2, aw2, pQ1, 0);
  k_conv3x3<<<dim3(16,6,8),256>>>(pA1, aw3, pV , 0);
  k_conv3x3<<<dim3(16,6,8),256>>>(pA2, wc2, pW2, 0);

  /* attention weights */
  k_attn_gemm<<<dim3(9,8),256>>>(pK1, pQ1, pATTN);
  k_softmax  <<<dim3(96,8),256>>>(pATTN);

  /* per-example attention conv */
  k_conv3x3<<<dim3(16,6,8),256>>>(pV, pATTN, pAO, 1);

  /* layer-norm stats for AO and W2 */
  k_reduce_ss<<<dim3(64,8),256>>>(pAO, 2);
  k_reduce_ss<<<dim3(64,8),256>>>(pW2, 3);
  k_combine  <<<1,32>>>(2);
  k_combine  <<<1,32>>>(3);

  /* fused epilogue */
  k_final<<<dim3(HW/128,8),256>>>(wf, bf, pAO, pW2, pA1, pXR, (float*)d_out);
}

// round 2
// speedup vs baseline: 1.0162x; 1.0162x over previous
#include <cuda_runtime.h>
#include <math.h>

#define Bn 8
#define Cc 96
#define Hh 128
#define Wd 128
#define HW (Hh*Wd)
#define NPB (Cc*HW)            /* 1,572,864 per-sample */
#define NELEM (Bn*NPB)         /* 12,582,912 */
#define TOTF 1572864.0f
#define EPSLN 1e-5f

/* ---------------- scratch (device globals; no allocation) ---------------- */
__device__ float4 g_bA1[NELEM/4];   /* x1 out of relu-split  */
__device__ float4 g_bA2[NELEM/4];   /* x2 out of relu-split  */
__device__ float4 g_bXR[NELEM/4];   /* residual xr           */
__device__ float4 g_bK1[NELEM/4];   /* conv(A1, aw1)         */
__device__ float4 g_bQ1[NELEM/4];   /* conv(A2, aw2)         */
__device__ float4 g_bV [NELEM/4];   /* conv(A1, aw3)         */
__device__ float4 g_bW2[NELEM/4];   /* conv(A2, w_conv2)     */
__device__ float4 g_bAO[NELEM/4];   /* attention conv output */
__device__ float  g_ATTN[Bn*Cc*Cc*9];
__device__ float  g_part[4*8*64*4]; /* [slot][b][block][comp] */
__device__ float  g_red [4*8*4];    /* [slot][b][comp]        */
__device__ float  g_coef[8*8];

/* ---------------- helpers ---------------- */
__device__ __forceinline__ float warp_sum(float v){
  #pragma unroll
  for (int o=16;o;o>>=1) v += __shfl_xor_sync(0xffffffffu, v, o);
  return v;
}

/* ---------------- reductions (deterministic: partials + ordered combine) -- */
__global__ void k_reduce_ss(const float* __restrict__ in, int slot)
{
  __shared__ float sm[2][8];
  int b = blockIdx.y;
  const float4* p = (const float4*)in + (size_t)b*(NPB/4);
  float s=0.f, ss=0.f;
  for (int i = blockIdx.x*blockDim.x + threadIdx.x; i < NPB/4; i += gridDim.x*blockDim.x){
    float4 v = p[i];
    s  += (v.x+v.y)+(v.z+v.w);
    ss += v.x*v.x + v.y*v.y + v.z*v.z + v.w*v.w;
  }
  s = warp_sum(s); ss = warp_sum(ss);
  int lane = threadIdx.x&31, w = threadIdx.x>>5;
  if (lane==0){ sm[0][w]=s; sm[1][w]=ss; }
  __syncthreads();
  if (threadIdx.x==0){
    float a=0.f,c=0.f;
    for (int i=0;i<8;i++){ a+=sm[0][i]; c+=sm[1][i]; }
    float* o = &g_part[((slot*8+b)*64 + blockIdx.x)*4];
    o[0]=a; o[1]=c;
  }
}

__global__ void k_reduce_pos(const float* __restrict__ in)
{
  __shared__ float sm[3][8];
  int b = blockIdx.y;
  float m = g_red[(0*8+b)*4+0] * (1.0f/TOTF);
  const float4* p = (const float4*)in + (size_t)b*(NPB/4);
  float P=0.f, PP=0.f, cnt=0.f;
  for (int i = blockIdx.x*blockDim.x + threadIdx.x; i < NPB/4; i += gridDim.x*blockDim.x){
    float4 v = p[i];
    float a;
    a=v.x-m; if(a>0.f){P+=a;PP+=a*a;cnt+=1.f;}
    a=v.y-m; if(a>0.f){P+=a;PP+=a*a;cnt+=1.f;}
    a=v.z-m; if(a>0.f){P+=a;PP+=a*a;cnt+=1.f;}
    a=v.w-m; if(a>0.f){P+=a;PP+=a*a;cnt+=1.f;}
  }
  P = warp_sum(P); PP = warp_sum(PP); cnt = warp_sum(cnt);
  int lane = threadIdx.x&31, w = threadIdx.x>>5;
  if (lane==0){ sm[0][w]=P; sm[1][w]=PP; sm[2][w]=cnt; }
  __syncthreads();
  if (threadIdx.x==0){
    float a=0.f,c=0.f,d=0.f;
    for (int i=0;i<8;i++){ a+=sm[0][i]; c+=sm[1][i]; d+=sm[2][i]; }
    float* o = &g_part[((1*8+b)*64 + blockIdx.x)*4];
    o[0]=a; o[1]=c; o[2]=d;
  }
}

__global__ void k_combine(int slot)
{
  int t = threadIdx.x;
  if (t < 32){
    int b = t>>2, c = t&3;
    float s=0.f;
    const float* p = &g_part[((slot*8+b)*64)*4 + c];
    for (int i=0;i<64;i++) s += p[i*4];
    g_red[(slot*8+b)*4 + c] = s;
  }
}

/* ---------------- closed-form relu-split-norm coefficients ---------------- */
__global__ void k_coef()
{
  int b = threadIdx.x;
  if (b >= 8) return;
  float S  = g_red[(0*8+b)*4+0], SS = g_red[(0*8+b)*4+1];
  float P  = g_red[(1*8+b)*4+0], PP = g_red[(1*8+b)*4+1], np = g_red[(1*8+b)*4+2];
  float T = TOTF;
  float m = S/T;
  float neg = T - np;
  float avg1 = P/np;
  float mean1 = (P + avg1*neg)/T;
  float var1  = (PP + avg1*avg1*neg)/T - mean1*mean1;
  float inv1  = 1.0f/sqrtf(var1 + EPSLN);
  float s1    = sqrtf(np/T);
  float SSc = SS - S*S/T;
  float QQ  = SSc - PP;
  float avg2  = -P/neg;
  float mean2 = (-P + avg2*np)/T;
  float var2  = (QQ + avg2*avg2*np)/T - mean2*mean2;
  float inv2  = 1.0f/sqrtf(var2 + EPSLN);
  float s2    = sqrtf(neg/T);
  float* c = &g_coef[b*8];
  c[0]=m; c[1]=mean1; c[2]=s1*inv1; c[3]=s1*(avg1-mean1)*inv1;
  c[4]=mean2; c[5]=s2*inv2; c[6]=s2*(avg2-mean2)*inv2;
}

/* ---------------- elementwise: produce A1, A2, XR ---------------- */
__global__ void k_elemwise(const float4* __restrict__ x,
    const float* __restrict__ sc1p, const float* __restrict__ sc2p,
    const float* __restrict__ rcp,  const float* __restrict__ nc1p,
    const float* __restrict__ nc2p,
    float4* __restrict__ A1, float4* __restrict__ A2, float4* __restrict__ XR)
{
  int idx = blockIdx.x*blockDim.x + threadIdx.x;
  if (idx >= NELEM/4) return;
  int b = idx / (NPB/4);
  const float* cf = &g_coef[b*8];
  float m=cf[0], mean1=cf[1], g1=cf[2], c1n=cf[3], mean2=cf[4], g2=cf[5], c2n=cf[6];
  float sc1=sc1p[0], sc2=sc2p[0], rc=rcp[0], nc1=nc1p[0], nc2=nc2p[0];
  float4 xv = x[idx];
  float xi[4] = {xv.x, xv.y, xv.z, xv.w};
  float o1[4], o2[4], o3[4];
  #pragma unroll
  for (int k=0;k<4;k++){
    float xc = xi[k]-m;
    float x1n, x2n, v1, v2;
    if (xc > 0.f){ x1n=(xc-mean1)*g1; x2n=c2n; v1=sc1*xc+x1n; v2=x2n; }
    else         { x1n=c1n; x2n=(xc-mean2)*g2; v1=x1n; v2=sc2*xc+x2n; }
    o1[k]=v1; o2[k]=v2; o3[k]=0.5f*(nc1*x1n+nc2*x2n)+rc*xc;
  }
  A1[idx]=make_float4(o1[0],o1[1],o1[2],o1[3]);
  A2[idx]=make_float4(o2[0],o2[1],o2[2],o2[3]);
  XR[idx]=make_float4(o3[0],o3[1],o3[2],o3[3]);
}

/* ---------------- dual 3x3 conv: two weight sets, one shared input ----------
   block: 256 thr, tile 32(w) x 16(h), 16 oc. thread = 4 oc x 8 px x 2 convs.
   per ic: 1152 FFMA vs 102 LDS  -> FMA-bound. 2 blocks/SM for load overlap.  */
__global__ void __launch_bounds__(256, 2)
k_conv3x3_dual(const float* __restrict__ in,
               const float* __restrict__ wA, const float* __restrict__ wB,
               float* __restrict__ outA, float* __restrict__ outB)
{
  __shared__ float s_in[4][18*35];       /* 4 ic x (16+2) x (32+2), stride 35 */
  __shared__ float s_w[2][16*36];        /* [conv][oc][ic4][9]                */
  const int b   = blockIdx.z;
  const int oc0 = blockIdx.y * 16;
  const int tileY = (blockIdx.x >> 2) * 16;
  const int tileX = (blockIdx.x & 3) * 32;
  const int tid = threadIdx.x;
  const int r   = tid >> 4;              /* 0..15 */
  const int xg  = (tid >> 2) & 3;        /* 0..3  */
  const int ocq = tid & 3;               /* 0..3  */
  const int x0  = xg * 8;

  float acc[2][4][8];
  #pragma unroll
  for (int c=0;c<2;c++)
    #pragma unroll
    for (int j=0;j<4;j++)
      #pragma unroll
      for (int p=0;p<8;p++) acc[c][j][p]=0.f;

  for (int ic0 = 0; ic0 < Cc; ic0 += 4){
    for (int idx = tid; idx < 4*18*34; idx += 256){
      int ic  = idx / 612;
      int rem = idx - ic*612;
      int iy  = rem / 34, ix = rem - iy*34;
      int gy = tileY + iy - 1, gx = tileX + ix - 1;
      float v = 0.f;
      if ((unsigned)gy < 128u && (unsigned)gx < 128u)
        v = in[(((size_t)b*Cc + ic0+ic)*Hh + gy)*Wd + gx];
      s_in[ic][iy*35+ix] = v;
    }
    for (int idx = tid; idx < 1152; idx += 256){
      int cv  = idx / 576;
      int rem = idx - cv*576;
      int oc  = rem / 36;
      int rem2= rem - oc*36;
      int ic  = rem2 / 9, k = rem2 - ic*9;
      const float* wp = cv ? wB : wA;
      s_w[cv][oc*36 + rem2] = wp[((size_t)(oc0+oc)*Cc + ic0+ic)*9 + k];
    }
    __syncthreads();
    #pragma unroll
    for (int ic=0; ic<4; ic++){
      float iv[3][10];
      #pragma unroll
      for (int dr=0; dr<3; dr++){
        #pragma unroll
        for (int dc=0; dc<10; dc++)
          iv[dr][dc] = s_in[ic][(r+dr)*35 + x0 + dc];
      }
      #pragma unroll
      for (int cv=0; cv<2; cv++){
        #pragma unroll
        for (int j=0; j<4; j++){
          const float* wp = &s_w[cv][(ocq*4+j)*36 + ic*9];
          float w0=wp[0],w1=wp[1],w2=wp[2],w3=wp[3],w4=wp[4],w5=wp[5],w6=wp[6],w7=wp[7],w8=wp[8];
          #pragma unroll
          for (int p=0;p<8;p++){
            float a = acc[cv][j][p];
            a += iv[0][p]*w0; a += iv[0][p+1]*w1; a += iv[0][p+2]*w2;
            a += iv[1][p]*w3; a += iv[1][p+1]*w4; a += iv[1][p+2]*w5;
            a += iv[2][p]*w6; a += iv[2][p+1]*w7; a += iv[2][p+2]*w8;
            acc[cv][j][p]=a;
          }
        }
      }
    }
    __syncthreads();
  }
  #pragma unroll
  for (int cv=0; cv<2; cv++){
    float* op = cv ? outB : outA;
    #pragma unroll
    for (int j=0; j<4; j++){
      int oc = oc0 + ocq*4 + j;
      size_t off = (((size_t)b*Cc + oc)*Hh + tileY + r)*Wd + tileX + x0;
      *(float4*)(op+off)   = make_float4(acc[cv][j][0],acc[cv][j][1],acc[cv][j][2],acc[cv][j][3]);
      *(float4*)(op+off+4) = make_float4(acc[cv][j][4],acc[cv][j][5],acc[cv][j][6],acc[cv][j][7]);
    }
  }
}

/* ---------------- single 3x3 conv, per-batch weights (attention conv) -----
   block: 256 thr, tile 32x16, 32 oc. thread = 8 oc x 8 px.                  */
__global__ void __launch_bounds__(256, 2)
k_conv3x3_pb(const float* __restrict__ in, const float* __restrict__ w,
             float* __restrict__ out)
{
  __shared__ float s_in[4][18*35];
  __shared__ float s_w[32*36];           /* [oc][ic4][9] */
  const int b   = blockIdx.z;
  const int oc0 = blockIdx.y * 32;
  const int tileY = (blockIdx.x >> 2) * 16;
  const int tileX = (blockIdx.x & 3) * 32;
  const int tid = threadIdx.x;
  const int r   = tid >> 4;
  const int xg  = (tid >> 2) & 3;
  const int och = tid & 3;
  const int x0  = xg * 8;
  const float* wb = w + (size_t)b*Cc*Cc*9;

  float acc[8][8];
  #pragma unroll
  for (int j=0;j<8;j++)
    #pragma unroll
    for (int p=0;p<8;p++) acc[j][p]=0.f;

  for (int ic0 = 0; ic0 < Cc; ic0 += 4){
    for (int idx = tid; idx < 4*18*34; idx += 256){
      int ic  = idx / 612;
      int rem = idx - ic*612;
      int iy  = rem / 34, ix = rem - iy*34;
      int gy = tileY + iy - 1, gx = tileX + ix - 1;
      float v = 0.f;
      if ((unsigned)gy < 128u && (unsigned)gx < 128u)
        v = in[(((size_t)b*Cc + ic0+ic)*Hh + gy)*Wd + gx];
      s_in[ic][iy*35+ix] = v;
    }
    for (int idx = tid; idx < 1152; idx += 256){
      int oc  = idx / 36;
      int rem2= idx - oc*36;
      int ic  = rem2 / 9, k = rem2 - ic*9;
      s_w[idx] = wb[((size_t)(oc0+oc)*Cc + ic0+ic)*9 + k];
    }
    __syncthreads();
    #pragma unroll
    for (int ic=0; ic<4; ic++){
      float iv[3][10];
      #pragma unroll
      for (int dr=0; dr<3; dr++){
        #pragma unroll
        for (int dc=0; dc<10; dc++)
          iv[dr][dc] = s_in[ic][(r+dr)*35 + x0 + dc];
      }
      #pragma unroll
      for (int j=0; j<8; j++){
        const float* wp = &s_w[(och*8+j)*36 + ic*9];
        float w0=wp[0],w1=wp[1],w2=wp[2],w3=wp[3],w4=wp[4],w5=wp[5],w6=wp[6],w7=wp[7],w8=wp[8];
        #pragma unroll
        for (int p=0;p<8;p++){
          float a = acc[j][p];
          a += iv[0][p]*w0; a += iv[0][p+1]*w1; a += iv[0][p+2]*w2;
          a += iv[1][p]*w3; a += iv[1][p+1]*w4; a += iv[1][p+2]*w5;
          a += iv[2][p]*w6; a += iv[2][p+1]*w7; a += iv[2][p+2]*w8;
          acc[j][p]=a;
        }
      }
    }
    __syncthreads();
  }
  #pragma unroll
  for (int j=0; j<8; j++){
    int oc = oc0 + och*8 + j;
    size_t off = (((size_t)b*Cc + oc)*Hh + tileY + r)*Wd + tileX + x0;
    *(float4*)(out+off)   = make_float4(acc[j][0],acc[j][1],acc[j][2],acc[j][3]);
    *(float4*)(out+off+4) = make_float4(acc[j][4],acc[j][5],acc[j][6],acc[j][7]);
  }
}

/* ---------------- attention GEMM: attn[b,q,c,k] = sum_l K[c,pix]Q[q,pix] --- */
__global__ void k_attn_gemm(const float* __restrict__ K1, const float* __restrict__ Q1,
                            float* __restrict__ attn)
{
  __shared__ float sk[16][96];
  __shared__ float sq[16][96];
  const int kidx = blockIdx.x;          /* 0..8 */
  const int kh = kidx/3, kw = kidx%3;
  const int b = blockIdx.y;
  const int tid = threadIdx.x;
  const int q0 = (tid >> 4) * 6;
  const int c0 = (tid & 15) * 6;
  float acc[6][6];
  #pragma unroll
  for (int i=0;i<6;i++){
    #pragma unroll
    for (int j=0;j<6;j++) acc[i][j]=0.f;
  }

  for (int l0 = 0; l0 < 1764; l0 += 16){
    for (int idx = tid; idx < 1536; idx += 256){
      int c = idx >> 4; int ll = idx & 15;
      int l = l0 + ll;
      float kv=0.f, qv=0.f;
      if (l < 1764){
        int ho = l/42, wo = l - ho*42;
        int pix = (3*ho+kh)*Wd + (3*wo+kw);
        size_t off = ((size_t)b*Cc + c)*HW + pix;
        kv = K1[off]; qv = Q1[off];
      }
      sk[ll][c]=kv; sq[ll][c]=qv;
    }
    __syncthreads();
    #pragma unroll
    for (int ll=0; ll<16; ll++){
      float qv[6], cv[6];
      #pragma unroll
      for (int i=0;i<6;i++) qv[i]=sq[ll][q0+i];
      #pragma unroll
      for (int j=0;j<6;j++) cv[j]=sk[ll][c0+j];
      #pragma unroll
      for (int i=0;i<6;i++){
        #pragma unroll
        for (int j=0;j<6;j++) acc[i][j] += qv[i]*cv[j];
      }
    }
    __syncthreads();
  }
  #pragma unroll
  for (int i=0;i<6;i++){
    #pragma unroll
    for (int j=0;j<6;j++)
      attn[((size_t)b*Cc + q0+i)*864 + (size_t)(c0+j)*9 + kidx] = acc[i][j];
  }
}

/* ---------------- softmax over 864, scaled by 1/sqrt(864) ---------------- */
__global__ void k_softmax(float* __restrict__ attn)
{
  __shared__ float sm[8];
  __shared__ float bc;
  const int b = blockIdx.y, q = blockIdx.x, tid = threadIdx.x;
  float* row = attn + ((size_t)(b*Cc+q))*864;
  const float scale = 0.034020690871988586f;   /* 1/sqrt(864) */
  float mx = -1e30f;
  for (int i=tid;i<864;i+=256) mx = fmaxf(mx, row[i]*scale);
  #pragma unroll
  for (int o=16;o;o>>=1) mx = fmaxf(mx, __shfl_xor_sync(0xffffffffu, mx, o));
  if ((tid&31)==0) sm[tid>>5]=mx;
  __syncthreads();
  if (tid==0){ float v=sm[0]; for(int i=1;i<8;i++) v=fmaxf(v,sm[i]); bc=v; }
  __syncthreads();
  mx = bc;
  float s=0.f;
  for (int i=tid;i<864;i+=256){ float e = expf(row[i]*scale - mx); row[i]=e; s+=e; }
  s = warp_sum(s);
  __syncthreads();
  if ((tid&31)==0) sm[tid>>5]=s;
  __syncthreads();
  if (tid==0){ float v=0.f; for(int i=0;i<8;i++) v+=sm[i]; bc=1.0f/v; }
  __syncthreads();
  float inv = bc;
  for (int i=tid;i<864;i+=256) row[i]*=inv;
}

/* ---------------- final: LN(AO), LN(W2)*A1, 1x1 conv 192->96, +XR +bias ---
   thread = 12 oc x 4 px (float4). ws ii-major so weight LDS vectorizes.     */
__global__ void __launch_bounds__(256)
k_final(const float* __restrict__ wf, const float* __restrict__ bias,
        const float* __restrict__ AO, const float* __restrict__ W2,
        const float* __restrict__ A1, const float* __restrict__ XR,
        float* __restrict__ out)
{
  __shared__ float yv[48][128];
  __shared__ float ws[48][96];           /* [ii][oc] */
  const int b = blockIdx.y;
  const int pix0 = blockIdx.x * 128;
  const int tid = threadIdx.x;
  const int g = tid >> 5;     /* 0..7 : 12 out-chans each */
  const int s = tid & 31;     /* 4 px: s*4 .. s*4+3       */

  float S1 = g_red[(2*8+b)*4+0], SS1 = g_red[(2*8+b)*4+1];
  float m1 = S1*(1.0f/TOTF);
  float inv1 = 1.0f/sqrtf(SS1*(1.0f/TOTF) - m1*m1 + EPSLN);
  float S2 = g_red[(3*8+b)*4+0], SS2 = g_red[(3*8+b)*4+1];
  float m2 = S2*(1.0f/TOTF);
  float inv2 = 1.0f/sqrtf(SS2*(1.0f/TOTF) - m2*m2 + EPSLN);

  float acc[12][4];
  #pragma unroll
  for (int j=0;j<12;j++){
    #pragma unroll
    for (int k=0;k<4;k++) acc[j][k]=0.f;
  }

  for (int i0=0; i0<192; i0+=48){
    for (int idx=tid; idx<48*128; idx+=256){
      int ii = idx >> 7; int p = idx & 127;
      int i = i0+ii;
      float v;
      if (i < 96){
        v = (AO[((size_t)b*Cc+i)*HW + pix0+p]-m1)*inv1;
      } else {
        size_t o = ((size_t)b*Cc+(i-96))*HW + pix0+p;
        v = (W2[o]-m2)*inv2*A1[o];
      }
      yv[ii][p] = v;
    }
    for (int idx=tid; idx<48*96; idx+=256){
      int ii = idx/96, o = idx-ii*96;
      ws[ii][o] = wf[(size_t)o*192 + i0+ii];
    }
    __syncthreads();
    #pragma unroll 4
    for (int ii=0; ii<48; ii++){
      float4 v = *(const float4*)&yv[ii][s*4];
      float4 w0 = *(const float4*)&ws[ii][g*12];
      float4 w1 = *(const float4*)&ws[ii][g*12+4];
      float4 w2 = *(const float4*)&ws[ii][g*12+8];
      float wv[12] = {w0.x,w0.y,w0.z,w0.w, w1.x,w1.y,w1.z,w1.w, w2.x,w2.y,w2.z,w2.w};
      #pragma unroll
      for (int j=0;j<12;j++){
        acc[j][0] += wv[j]*v.x; acc[j][1] += wv[j]*v.y;
        acc[j][2] += wv[j]*v.z; acc[j][3] += wv[j]*v.w;
      }
    }
    __syncthreads();
  }
  #pragma unroll
  for (int j=0;j<12;j++){
    int o = g*12+j;
    size_t off = ((size_t)b*Cc+o)*HW + pix0 + s*4;
    float bb = bias[o];
    float4 xr = *(const float4*)(XR+off);
    float4 ov = make_float4(xr.x+bb+acc[j][0], xr.y+bb+acc[j][1],
                            xr.z+bb+acc[j][2], xr.w+bb+acc[j][3]);
    *(float4*)(out+off) = ov;
  }
}

/* ---------------- host ---------------- */
extern "C" void kernel_launch(void* const* d_in, const int* in_sizes, int n_in,
                              void* d_out, int out_size)
{
  const float* x    = (const float*)d_in[0];
  const float* wc2  = (const float*)d_in[1];
  const float* aw1  = (const float*)d_in[2];
  const float* aw2  = (const float*)d_in[3];
  const float* aw3  = (const float*)d_in[4];
  const float* wf   = (const float*)d_in[5];
  const float* bf   = (const float*)d_in[6];
  const float* sc1  = (const float*)d_in[7];
  const float* sc2  = (const float*)d_in[8];
  const float* rc   = (const float*)d_in[9];
  const float* nc1  = (const float*)d_in[10];
  const float* nc2  = (const float*)d_in[11];

  float *pA1,*pA2,*pXR,*pK1,*pQ1,*pV,*pW2,*pAO,*pATTN;
  cudaGetSymbolAddress((void**)&pA1, g_bA1);
  cudaGetSymbolAddress((void**)&pA2, g_bA2);
  cudaGetSymbolAddress((void**)&pXR, g_bXR);
  cudaGetSymbolAddress((void**)&pK1, g_bK1);
  cudaGetSymbolAddress((void**)&pQ1, g_bQ1);
  cudaGetSymbolAddress((void**)&pV , g_bV );
  cudaGetSymbolAddress((void**)&pW2, g_bW2);
  cudaGetSymbolAddress((void**)&pAO, g_bAO);
  cudaGetSymbolAddress((void**)&pATTN, g_ATTN);

  /* stats of x (deterministic two-stage) */
  k_reduce_ss <<<dim3(64,8),256>>>(x, 0);
  k_combine   <<<1,32>>>(0);
  k_reduce_pos<<<dim3(64,8),256>>>(x);
  k_combine   <<<1,32>>>(1);
  k_coef      <<<1,8>>>();

  /* relu-split-norm elementwise */
  k_elemwise<<<NELEM/4/256,256>>>((const float4*)x, sc1,sc2,rc,nc1,nc2,
                                  (float4*)pA1,(float4*)pA2,(float4*)pXR);

  /* two dual 3x3 conv passes (shared inputs) */
  k_conv3x3_dual<<<dim3(32,6,8),256>>>(pA1, aw1, aw3, pK1, pV );
  k_conv3x3_dual<<<dim3(32,6,8),256>>>(pA2, aw2, wc2, pQ1, pW2);

  /* attention weights */
  k_attn_gemm<<<dim3(9,8),256>>>(pK1, pQ1, pATTN);
  k_softmax  <<<dim3(96,8),256>>>(pATTN);

  /* per-example attention conv */
  k_conv3x3_pb<<<dim3(32,3,8),256>>>(pV, pATTN, pAO);

  /* layer-norm stats for AO and W2 */
  k_reduce_ss<<<dim3(64,8),256>>>(pAO, 2);
  k_reduce_ss<<<dim3(64,8),256>>>(pW2, 3);
  k_combine  <<<1,32>>>(2);
  k_combine  <<<1,32>>>(3);

  /* fused epilogue */
  k_final<<<dim3(HW/128,8),256>>>(wf, bf, pAO, pW2, pA1, pXR, (float*)d_out);
}

// round 4
// speedup vs baseline: 1.7269x; 1.6993x over previous
#include <cuda_runtime.h>
#include <math.h>

#define Bn 8
#define Cc 96
#define Hh 128
#define Wd 128
#define HW (Hh*Wd)
#define NPB (Cc*HW)            /* 1,572,864 per-sample */
#define NELEM (Bn*NPB)         /* 12,582,912 */
#define TOTF 1572864.0f
#define EPSLN 1e-5f

/* ---------------- scratch (device globals; no allocation) ---------------- */
__device__ float4 g_bA1[NELEM/4];
__device__ float4 g_bA2[NELEM/4];
__device__ float4 g_bXR[NELEM/4];
__device__ float4 g_bK1[NELEM/4];
__device__ float4 g_bQ1[NELEM/4];
__device__ float4 g_bV [NELEM/4];
__device__ float4 g_bW2[NELEM/4];
__device__ float4 g_bAO[NELEM/4];
__device__ float  g_ATTN [Bn*Cc*Cc*9];      /* raw attn logits            */
__device__ float  g_ATTNT[Bn*9*Cc*Cc];      /* softmaxed, [b][tap][ic][oc] */
__device__ float  g_WT[4*9*Cc*Cc];          /* fixed weights [w][tap][ic][oc] */
__device__ float  g_part[4*8*64*4];
__device__ float  g_red [4*8*4];
__device__ float  g_coef[8*8];

/* ---------------- helpers ---------------- */
__device__ __forceinline__ float warp_sum(float v){
  #pragma unroll
  for (int o=16;o;o>>=1) v += __shfl_xor_sync(0xffffffffu, v, o);
  return v;
}
__device__ __forceinline__ unsigned f2tf(float f){
  unsigned r; asm("cvt.rna.tf32.f32 %0, %1;" : "=r"(r) : "f"(f)); return r;
}
__device__ __forceinline__ void mma_tf32(float c[4], const unsigned a[4],
                                         unsigned b0, unsigned b1){
  asm volatile("mma.sync.aligned.m16n8k8.row.col.f32.tf32.tf32.f32 "
               "{%0,%1,%2,%3},{%4,%5,%6,%7},{%8,%9},{%0,%1,%2,%3};"
               : "+f"(c[0]),"+f"(c[1]),"+f"(c[2]),"+f"(c[3])
               : "r"(a[0]),"r"(a[1]),"r"(a[2]),"r"(a[3]),"r"(b0),"r"(b1));
}

/* ---------------- reductions (deterministic) ---------------- */
__global__ void k_reduce_ss(const float* __restrict__ in, int slot)
{
  __shared__ float sm[2][8];
  int b = blockIdx.y;
  const float4* p = (const float4*)in + (size_t)b*(NPB/4);
  float s=0.f, ss=0.f;
  for (int i = blockIdx.x*blockDim.x + threadIdx.x; i < NPB/4; i += gridDim.x*blockDim.x){
    float4 v = p[i];
    s  += (v.x+v.y)+(v.z+v.w);
    ss += v.x*v.x + v.y*v.y + v.z*v.z + v.w*v.w;
  }
  s = warp_sum(s); ss = warp_sum(ss);
  int lane = threadIdx.x&31, w = threadIdx.x>>5;
  if (lane==0){ sm[0][w]=s; sm[1][w]=ss; }
  __syncthreads();
  if (threadIdx.x==0){
    float a=0.f,c=0.f;
    for (int i=0;i<8;i++){ a+=sm[0][i]; c+=sm[1][i]; }
    float* o = &g_part[((slot*8+b)*64 + blockIdx.x)*4];
    o[0]=a; o[1]=c;
  }
}

__global__ void k_reduce_pos(const float* __restrict__ in)
{
  __shared__ float sm[3][8];
  int b = blockIdx.y;
  float m = g_red[(0*8+b)*4+0] * (1.0f/TOTF);
  const float4* p = (const float4*)in + (size_t)b*(NPB/4);
  float P=0.f, PP=0.f, cnt=0.f;
  for (int i = blockIdx.x*blockDim.x + threadIdx.x; i < NPB/4; i += gridDim.x*blockDim.x){
    float4 v = p[i];
    float a;
    a=v.x-m; if(a>0.f){P+=a;PP+=a*a;cnt+=1.f;}
    a=v.y-m; if(a>0.f){P+=a;PP+=a*a;cnt+=1.f;}
    a=v.z-m; if(a>0.f){P+=a;PP+=a*a;cnt+=1.f;}
    a=v.w-m; if(a>0.f){P+=a;PP+=a*a;cnt+=1.f;}
  }
  P = warp_sum(P); PP = warp_sum(PP); cnt = warp_sum(cnt);
  int lane = threadIdx.x&31, w = threadIdx.x>>5;
  if (lane==0){ sm[0][w]=P; sm[1][w]=PP; sm[2][w]=cnt; }
  __syncthreads();
  if (threadIdx.x==0){
    float a=0.f,c=0.f,d=0.f;
    for (int i=0;i<8;i++){ a+=sm[0][i]; c+=sm[1][i]; d+=sm[2][i]; }
    float* o = &g_part[((1*8+b)*64 + blockIdx.x)*4];
    o[0]=a; o[1]=c; o[2]=d;
  }
}

__global__ void k_combine(int slot)
{
  int t = threadIdx.x;
  if (t < 32){
    int b = t>>2, c = t&3;
    float s=0.f;
    const float* p = &g_part[((slot*8+b)*64)*4 + c];
    for (int i=0;i<64;i++) s += p[i*4];
    g_red[(slot*8+b)*4 + c] = s;
  }
}

/* ---------------- closed-form relu-split-norm coefficients ---------------- */
__global__ void k_coef()
{
  int b = threadIdx.x;
  if (b >= 8) return;
  float S  = g_red[(0*8+b)*4+0], SS = g_red[(0*8+b)*4+1];
  float P  = g_red[(1*8+b)*4+0], PP = g_red[(1*8+b)*4+1], np = g_red[(1*8+b)*4+2];
  float T = TOTF;
  float m = S/T;
  float neg = T - np;
  float avg1 = P/np;
  float mean1 = (P + avg1*neg)/T;
  float var1  = (PP + avg1*avg1*neg)/T - mean1*mean1;
  float inv1  = 1.0f/sqrtf(var1 + EPSLN);
  float s1    = sqrtf(np/T);
  float SSc = SS - S*S/T;
  float QQ  = SSc - PP;
  float avg2  = -P/neg;
  float mean2 = (-P + avg2*np)/T;
  float var2  = (QQ + avg2*avg2*np)/T - mean2*mean2;
  float inv2  = 1.0f/sqrtf(var2 + EPSLN);
  float s2    = sqrtf(neg/T);
  float* c = &g_coef[b*8];
  c[0]=m; c[1]=mean1; c[2]=s1*inv1; c[3]=s1*(avg1-mean1)*inv1;
  c[4]=mean2; c[5]=s2*inv2; c[6]=s2*(avg2-mean2)*inv2;
}

/* ---------------- elementwise: produce A1, A2, XR ---------------- */
__global__ void k_elemwise(const float4* __restrict__ x,
    const float* __restrict__ sc1p, const float* __restrict__ sc2p,
    const float* __restrict__ rcp,  const float* __restrict__ nc1p,
    const float* __restrict__ nc2p,
    float4* __restrict__ A1, float4* __restrict__ A2, float4* __restrict__ XR)
{
  int idx = blockIdx.x*blockDim.x + threadIdx.x;
  if (idx >= NELEM/4) return;
  int b = idx / (NPB/4);
  const float* cf = &g_coef[b*8];
  float m=cf[0], mean1=cf[1], g1=cf[2], c1n=cf[3], mean2=cf[4], g2=cf[5], c2n=cf[6];
  float sc1=sc1p[0], sc2=sc2p[0], rc=rcp[0], nc1=nc1p[0], nc2=nc2p[0];
  float4 xv = x[idx];
  float xi[4] = {xv.x, xv.y, xv.z, xv.w};
  float o1[4], o2[4], o3[4];
  #pragma unroll
  for (int k=0;k<4;k++){
    float xc = xi[k]-m;
    float x1n, x2n, v1, v2;
    if (xc > 0.f){ x1n=(xc-mean1)*g1; x2n=c2n; v1=sc1*xc+x1n; v2=x2n; }
    else         { x1n=c1n; x2n=(xc-mean2)*g2; v1=x1n; v2=sc2*xc+x2n; }
    o1[k]=v1; o2[k]=v2; o3[k]=0.5f*(nc1*x1n+nc2*x2n)+rc*xc;
  }
  A1[idx]=make_float4(o1[0],o1[1],o1[2],o1[3]);
  A2[idx]=make_float4(o2[0],o2[1],o2[2],o2[3]);
  XR[idx]=make_float4(o3[0],o3[1],o3[2],o3[3]);
}

/* ---------------- weight transpose + tf32 round: [oc][ic][9]->[tap][ic][oc] */
__global__ void k_wt(const float* __restrict__ w0, const float* __restrict__ w1,
                     const float* __restrict__ w2, const float* __restrict__ w3)
{
  int idx = blockIdx.x*blockDim.x + threadIdx.x;
  if (idx >= 4*9*Cc*Cc) return;
  int w   = idx / (9*Cc*Cc);
  int rem = idx - w*(9*Cc*Cc);
  int tap = rem / (Cc*Cc);
  int rem2= rem - tap*(Cc*Cc);
  int ic  = rem2 / Cc;
  int oc  = rem2 - ic*Cc;
  const float* src = (w==0)?w0:(w==1)?w1:(w==2)?w2:w3;
  float v = src[((size_t)oc*Cc + ic)*9 + tap];
  g_WT[idx] = __uint_as_float(f2tf(v));
}

/* ---------------- implicit-GEMM 3x3 conv via mma.sync tf32 ----------------
   block = (y row, batch). 8 warps = 2(oc:48) x 4(px:32). tile 96oc x 128px.
   K loop: 12 ic-chunks of 8, 9 taps, one m16n8k8 K-step each.               */
__global__ void __launch_bounds__(256, 2)
k_conv_mma(const float* __restrict__ in, const float* __restrict__ wt,
           long wstride, float* __restrict__ out)
{
  __shared__ unsigned Xs[8][3][132];   /* [ic8][row][x+1], tf32 bits */
  __shared__ unsigned Ws[9][8][104];   /* [tap][ic8][oc] (pad 104)   */
  const int b = blockIdx.y;
  const int y = blockIdx.x;
  const float* wb = wt + (size_t)b*wstride;
  const int tid = threadIdx.x, wid = tid>>5, lane = tid&31;
  const int g = lane>>2, tig = lane&3;
  const int warpM = wid>>2, warpN = wid&3;
  const int oc0 = warpM*48, px0 = warpN*32;

  float c[3][4][4];
  #pragma unroll
  for (int m=0;m<3;m++)
    #pragma unroll
    for (int j=0;j<4;j++)
      #pragma unroll
      for (int k=0;k<4;k++) c[m][j][k]=0.f;

  for (int ic0 = 0; ic0 < Cc; ic0 += 8){
    /* input tile: 8 ic x 3 rows x 130 cols (x index -1..128), tf32-rounded */
    for (int idx = tid; idx < 8*3*130; idx += 256){
      int i  = idx / 390;
      int rem= idx - i*390;
      int ry = rem / 130, xx = rem - ry*130;
      int gy = y + ry - 1, gx = xx - 1;
      float v = 0.f;
      if ((unsigned)gy < 128u && (unsigned)gx < 128u)
        v = in[(((size_t)b*Cc + ic0+i)*Hh + gy)*Wd + gx];
      Xs[i][ry][xx] = f2tf(v);
    }
    /* weights (already tf32-rounded): [tap][ic][oc] */
    for (int idx = tid; idx < 9*8*96; idx += 256){
      int tap = idx / 768;
      int rem = idx - tap*768;
      int i   = rem / 96, oc = rem - i*96;
      Ws[tap][i][oc] = __float_as_uint(wb[((size_t)tap*Cc + ic0+i)*Cc + oc]);
    }
    __syncthreads();

    #pragma unroll
    for (int tap=0; tap<9; tap++){
      const int dy = tap/3, dx = tap%3;
      unsigned a[3][4];
      #pragma unroll
      for (int m=0;m<3;m++){
        int ocb = oc0 + 16*m + g;
        a[m][0] = Ws[tap][tig  ][ocb];
        a[m][1] = Ws[tap][tig  ][ocb+8];
        a[m][2] = Ws[tap][tig+4][ocb];
        a[m][3] = Ws[tap][tig+4][ocb+8];
      }
      #pragma unroll
      for (int j=0;j<4;j++){
        int xb = px0 + 8*j + g + dx;   /* Xs col = px + dx, col idx = x+1 */
        unsigned b0 = Xs[tig  ][dy][xb];
        unsigned b1 = Xs[tig+4][dy][xb];
        #pragma unroll
        for (int m=0;m<3;m++) mma_tf32(c[m][j], a[m], b0, b1);
      }
    }
    __syncthreads();
  }

  /* epilogue: c0=C[g][2tig], c1=C[g][2tig+1], c2=C[g+8][2tig], c3=+1 */
  #pragma unroll
  for (int m=0;m<3;m++){
    int r0 = oc0 + 16*m + g;
    #pragma unroll
    for (int j=0;j<4;j++){
      int px = px0 + 8*j + 2*tig;
      size_t o0 = (((size_t)b*Cc + r0  )*Hh + y)*Wd + px;
      size_t o1 = (((size_t)b*Cc + r0+8)*Hh + y)*Wd + px;
      *(float2*)(out+o0) = make_float2(c[m][j][0], c[m][j][1]);
      *(float2*)(out+o1) = make_float2(c[m][j][2], c[m][j][3]);
    }
  }
}

/* ---------------- attention GEMM: attn[b,q,c,k] = sum_l K[c,pix]Q[q,pix] --- */
__global__ void k_attn_gemm(const float* __restrict__ K1, const float* __restrict__ Q1,
                            float* __restrict__ attn)
{
  __shared__ float sk[16][96];
  __shared__ float sq[16][96];
  const int kidx = blockIdx.x;
  const int kh = kidx/3, kw = kidx%3;
  const int b = blockIdx.y;
  const int tid = threadIdx.x;
  const int q0 = (tid >> 4) * 6;
  const int c0 = (tid & 15) * 6;
  float acc[6][6];
  #pragma unroll
  for (int i=0;i<6;i++)
    #pragma unroll
    for (int j=0;j<6;j++) acc[i][j]=0.f;

  for (int l0 = 0; l0 < 1764; l0 += 16){
    for (int idx = tid; idx < 1536; idx += 256){
      int c = idx >> 4; int ll = idx & 15;
      int l = l0 + ll;
      float kv=0.f, qv=0.f;
      if (l < 1764){
        int ho = l/42, wo = l - ho*42;
        int pix = (3*ho+kh)*Wd + (3*wo+kw);
        size_t off = ((size_t)b*Cc + c)*HW + pix;
        kv = K1[off]; qv = Q1[off];
      }
      sk[ll][c]=kv; sq[ll][c]=qv;
    }
    __syncthreads();
    #pragma unroll
    for (int ll=0; ll<16; ll++){
      float qv[6], cv[6];
      #pragma unroll
      for (int i=0;i<6;i++) qv[i]=sq[ll][q0+i];
      #pragma unroll
      for (int j=0;j<6;j++) cv[j]=sk[ll][c0+j];
      #pragma unroll
      for (int i=0;i<6;i++)
        #pragma unroll
        for (int j=0;j<6;j++) acc[i][j] += qv[i]*cv[j];
    }
    __syncthreads();
  }
  #pragma unroll
  for (int i=0;i<6;i++)
    #pragma unroll
    for (int j=0;j<6;j++)
      attn[((size_t)b*Cc + q0+i)*864 + (size_t)(c0+j)*9 + kidx] = acc[i][j];
}

/* ------- softmax over 864; writes transposed tf32 weights [b][tap][c][q] -- */
__global__ void k_softmax(float* __restrict__ attn, float* __restrict__ attnT)
{
  __shared__ float sm[8];
  __shared__ float bc;
  const int b = blockIdx.y, q = blockIdx.x, tid = threadIdx.x;
  float* row = attn + ((size_t)(b*Cc+q))*864;
  const float scale = 0.034020690871988586f;   /* 1/sqrt(864) */
  float mx = -1e30f;
  for (int i=tid;i<864;i+=256) mx = fmaxf(mx, row[i]*scale);
  #pragma unroll
  for (int o=16;o;o>>=1) mx = fmaxf(mx, __shfl_xor_sync(0xffffffffu, mx, o));
  if ((tid&31)==0) sm[tid>>5]=mx;
  __syncthreads();
  if (tid==0){ float v=sm[0]; for(int i=1;i<8;i++) v=fmaxf(v,sm[i]); bc=v; }
  __syncthreads();
  mx = bc;
  float s=0.f;
  for (int i=tid;i<864;i+=256){ float e = expf(row[i]*scale - mx); row[i]=e; s+=e; }
  s = warp_sum(s);
  __syncthreads();
  if ((tid&31)==0) sm[tid>>5]=s;
  __syncthreads();
  if (tid==0){ float v=0.f; for(int i=0;i<8;i++) v+=sm[i]; bc=1.0f/v; }
  __syncthreads();
  float inv = bc;
  for (int i=tid;i<864;i+=256){
    float v = row[i]*inv;
    int cch = i/9, tap = i - 9*cch;
    attnT[(((size_t)b*9 + tap)*Cc + cch)*Cc + q] = __uint_as_float(f2tf(v));
  }
}

/* ---------------- final: LN(AO), LN(W2)*A1, 1x1 conv 192->96, +XR +bias --- */
__global__ void __launch_bounds__(256)
k_final(const float* __restrict__ wf, const float* __restrict__ bias,
        const float* __restrict__ AO, const float* __restrict__ W2,
        const float* __restrict__ A1, const float* __restrict__ XR,
        float* __restrict__ out)
{
  __shared__ float yv[48][128];
  __shared__ float ws[48][96];
  const int b = blockIdx.y;
  const int pix0 = blockIdx.x * 128;
  const int tid = threadIdx.x;
  const int g = tid >> 5;
  const int s = tid & 31;

  float S1 = g_red[(2*8+b)*4+0], SS1 = g_red[(2*8+b)*4+1];
  float m1 = S1*(1.0f/TOTF);
  float inv1 = 1.0f/sqrtf(SS1*(1.0f/TOTF) - m1*m1 + EPSLN);
  float S2 = g_red[(3*8+b)*4+0], SS2 = g_red[(3*8+b)*4+1];
  float m2 = S2*(1.0f/TOTF);
  float inv2 = 1.0f/sqrtf(SS2*(1.0f/TOTF) - m2*m2 + EPSLN);

  float acc[12][4];
  #pragma unroll
  for (int j=0;j<12;j++)
    #pragma unroll
    for (int k=0;k<4;k++) acc[j][k]=0.f;

  for (int i0=0; i0<192; i0+=48){
    for (int idx=tid; idx<48*128; idx+=256){
      int ii = idx >> 7; int p = idx & 127;
      int i = i0+ii;
      float v;
      if (i < 96){
        v = (AO[((size_t)b*Cc+i)*HW + pix0+p]-m1)*inv1;
      } else {
        size_t o = ((size_t)b*Cc+(i-96))*HW + pix0+p;
        v = (W2[o]-m2)*inv2*A1[o];
      }
      yv[ii][p] = v;
    }
    for (int idx=tid; idx<48*96; idx+=256){
      int ii = idx/96, o = idx-ii*96;
      ws[ii][o] = wf[(size_t)o*192 + i0+ii];
    }
    __syncthreads();
    #pragma unroll 4
    for (int ii=0; ii<48; ii++){
      float4 v = *(const float4*)&yv[ii][s*4];
      float4 w0 = *(const float4*)&ws[ii][g*12];
      float4 w1 = *(const float4*)&ws[ii][g*12+4];
      float4 w2 = *(const float4*)&ws[ii][g*12+8];
      float wv[12] = {w0.x,w0.y,w0.z,w0.w, w1.x,w1.y,w1.z,w1.w, w2.x,w2.y,w2.z,w2.w};
      #pragma unroll
      for (int j=0;j<12;j++){
        acc[j][0] += wv[j]*v.x; acc[j][1] += wv[j]*v.y;
        acc[j][2] += wv[j]*v.z; acc[j][3] += wv[j]*v.w;
      }
    }
    __syncthreads();
  }
  #pragma unroll
  for (int j=0;j<12;j++){
    int o = g*12+j;
    size_t off = ((size_t)b*Cc+o)*HW + pix0 + s*4;
    float bb = bias[o];
    float4 xr = *(const float4*)(XR+off);
    float4 ov = make_float4(xr.x+bb+acc[j][0], xr.y+bb+acc[j][1],
                            xr.z+bb+acc[j][2], xr.w+bb+acc[j][3]);
    *(float4*)(out+off) = ov;
  }
}

/* ---------------- host ---------------- */
extern "C" void kernel_launch(void* const* d_in, const int* in_sizes, int n_in,
                              void* d_out, int out_size)
{
  const float* x    = (const float*)d_in[0];
  const float* wc2  = (const float*)d_in[1];
  const float* aw1  = (const float*)d_in[2];
  const float* aw2  = (const float*)d_in[3];
  const float* aw3  = (const float*)d_in[4];
  const float* wf   = (const float*)d_in[5];
  const float* bf   = (const float*)d_in[6];
  const float* sc1  = (const float*)d_in[7];
  const float* sc2  = (const float*)d_in[8];
  const float* rc   = (const float*)d_in[9];
  const float* nc1  = (const float*)d_in[10];
  const float* nc2  = (const float*)d_in[11];

  float *pA1,*pA2,*pXR,*pK1,*pQ1,*pV,*pW2,*pAO,*pATTN,*pATTNT,*pWT;
  cudaGetSymbolAddress((void**)&pA1, g_bA1);
  cudaGetSymbolAddress((void**)&pA2, g_bA2);
  cudaGetSymbolAddress((void**)&pXR, g_bXR);
  cudaGetSymbolAddress((void**)&pK1, g_bK1);
  cudaGetSymbolAddress((void**)&pQ1, g_bQ1);
  cudaGetSymbolAddress((void**)&pV , g_bV );
  cudaGetSymbolAddress((void**)&pW2, g_bW2);
  cudaGetSymbolAddress((void**)&pAO, g_bAO);
  cudaGetSymbolAddress((void**)&pATTN, g_ATTN);
  cudaGetSymbolAddress((void**)&pATTNT, g_ATTNT);
  cudaGetSymbolAddress((void**)&pWT, g_WT);

  const long WSTRIDE = 9L*Cc*Cc;

  /* weight transpose (independent of data path) */
  k_wt<<<(4*9*Cc*Cc+255)/256,256>>>(aw1, aw2, aw3, wc2);

  /* stats of x */
  k_reduce_ss <<<dim3(64,8),256>>>(x, 0);
  k_combine   <<<1,32>>>(0);
  k_reduce_pos<<<dim3(64,8),256>>>(x);
  k_combine   <<<1,32>>>(1);
  k_coef      <<<1,8>>>();

  /* relu-split-norm elementwise */
  k_elemwise<<<NELEM/4/256,256>>>((const float4*)x, sc1,sc2,rc,nc1,nc2,
                                  (float4*)pA1,(float4*)pA2,(float4*)pXR);

  /* four fixed 3x3 convs on tensor cores */
  k_conv_mma<<<dim3(128,8),256>>>(pA1, pWT + 0*WSTRIDE, 0, pK1);
  k_conv_mma<<<dim3(128,8),256>>>(pA2, pWT + 1*WSTRIDE, 0, pQ1);
  k_conv_mma<<<dim3(128,8),256>>>(pA1, pWT + 2*WSTRIDE, 0, pV );
  k_conv_mma<<<dim3(128,8),256>>>(pA2, pWT + 3*WSTRIDE, 0, pW2);

  /* attention weights */
  k_attn_gemm<<<dim3(9,8),256>>>(pK1, pQ1, pATTN);
  k_softmax  <<<dim3(96,8),256>>>(pATTN, pATTNT);

  /* per-example attention conv on tensor cores */
  k_conv_mma<<<dim3(128,8),256>>>(pV, pATTNT, WSTRIDE, pAO);

  /* layer-norm stats for AO and W2 */
  k_reduce_ss<<<dim3(64,8),256>>>(pAO, 2);
  k_reduce_ss<<<dim3(64,8),256>>>(pW2, 3);
  k_combine  <<<1,32>>>(2);
  k_combine  <<<1,32>>>(3);

  /* fused epilogue */
  k_final<<<dim3(HW/128,8),256>>>(wf, bf, pAO, pW2, pA1, pXR, (float*)d_out);
}

// round 5
// speedup vs baseline: 3.6440x; 2.1102x over previous
#include <cuda_runtime.h>
#include <math.h>

#define Bn 8
#define Cc 96
#define Hh 128
#define Wd 128
#define HW (Hh*Wd)
#define NPB (Cc*HW)
#define NELEM (Bn*NPB)
#define TOTF 1572864.0f
#define EPSLN 1e-5f

/* ---------------- scratch (device globals; no allocation) ---------------- */
__device__ float4 g_bA1 [NELEM/4];   /* x1, fp32 (k_final)      */
__device__ float4 g_bA1t[NELEM/4];   /* x1, tf32-rounded        */
__device__ float4 g_bA2t[NELEM/4];   /* x2, tf32-rounded        */
__device__ float4 g_bXR [NELEM/4];
__device__ float4 g_bK1 [NELEM/4];
__device__ float4 g_bQ1 [NELEM/4];
__device__ float4 g_bV  [NELEM/4];   /* tf32-rounded            */
__device__ float4 g_bW2 [NELEM/4];
__device__ float4 g_bAO [NELEM/4];
__device__ float  g_ATTN [4*Bn*Cc*864];     /* 4 L-split slices          */
__device__ float  g_ATTNT[Bn*9*Cc*Cc];      /* softmaxed [b][tap][ic][oc] */
__device__ float  g_WT[4*9*Cc*Cc];          /* fixed w [w][tap][ic][oc]   */
__device__ float  g_part[4*8*64*4];
__device__ float  g_red [4*8*4];
__device__ float  g_coef[8*8];
__device__ int    g_ctr;

/* ---------------- helpers ---------------- */
__device__ __forceinline__ float warp_sum(float v){
  #pragma unroll
  for (int o=16;o;o>>=1) v += __shfl_xor_sync(0xffffffffu, v, o);
  return v;
}
__device__ __forceinline__ unsigned f2tf(float f){
  unsigned r; asm("cvt.rna.tf32.f32 %0, %1;" : "=r"(r) : "f"(f)); return r;
}
__device__ __forceinline__ void mma_tf32(float c[4], const unsigned a[4],
                                         unsigned b0, unsigned b1){
  asm volatile("mma.sync.aligned.m16n8k8.row.col.f32.tf32.tf32.f32 "
               "{%0,%1,%2,%3},{%4,%5,%6,%7},{%8,%9},{%0,%1,%2,%3};"
               : "+f"(c[0]),"+f"(c[1]),"+f"(c[2]),"+f"(c[3])
               : "r"(a[0]),"r"(a[1]),"r"(a[2]),"r"(a[3]),"r"(b0),"r"(b1));
}
__device__ __forceinline__ void cp16(float* dst, const float* src, int ok){
  unsigned d = (unsigned)__cvta_generic_to_shared(dst);
  asm volatile("cp.async.ca.shared.global [%0], [%1], 16, %2;"
               :: "r"(d), "l"(src), "r"(ok?16:0));
}

/* ---------------- reductions ---------------- */
__global__ void k_reduce_ss(const float* __restrict__ in, int slot)
{
  __shared__ float sm[2][8];
  int b = blockIdx.y;
  if (slot==0 && blockIdx.x==0 && b==0 && threadIdx.x==0) g_ctr = 0;
  const float4* p = (const float4*)in + (size_t)b*(NPB/4);
  float s=0.f, ss=0.f;
  for (int i = blockIdx.x*blockDim.x + threadIdx.x; i < NPB/4; i += gridDim.x*blockDim.x){
    float4 v = p[i];
    s  += (v.x+v.y)+(v.z+v.w);
    ss += v.x*v.x + v.y*v.y + v.z*v.z + v.w*v.w;
  }
  s = warp_sum(s); ss = warp_sum(ss);
  int lane = threadIdx.x&31, w = threadIdx.x>>5;
  if (lane==0){ sm[0][w]=s; sm[1][w]=ss; }
  __syncthreads();
  if (threadIdx.x==0){
    float a=0.f,c=0.f;
    for (int i=0;i<8;i++){ a+=sm[0][i]; c+=sm[1][i]; }
    float* o = &g_part[((slot*8+b)*64 + blockIdx.x)*4];
    o[0]=a; o[1]=c;
  }
}

/* pos-stats; self-computes mean; last block writes coefficients */
__global__ void k_reduce_pos(const float* __restrict__ in)
{
  __shared__ float sm[3][8];
  __shared__ float s_mu;
  __shared__ int   s_last;
  int b = blockIdx.y;
  int tid = threadIdx.x;
  if (tid==0){
    float S=0.f;
    const float* pp = &g_part[((0*8+b)*64)*4];
    for (int i=0;i<64;i++) S += pp[i*4];
    s_mu = S*(1.0f/TOTF);
  }
  __syncthreads();
  float m = s_mu;
  const float4* p = (const float4*)in + (size_t)b*(NPB/4);
  float P=0.f, PP=0.f, cnt=0.f;
  for (int i = blockIdx.x*blockDim.x + tid; i < NPB/4; i += gridDim.x*blockDim.x){
    float4 v = p[i];
    float a;
    a=v.x-m; if(a>0.f){P+=a;PP+=a*a;cnt+=1.f;}
    a=v.y-m; if(a>0.f){P+=a;PP+=a*a;cnt+=1.f;}
    a=v.z-m; if(a>0.f){P+=a;PP+=a*a;cnt+=1.f;}
    a=v.w-m; if(a>0.f){P+=a;PP+=a*a;cnt+=1.f;}
  }
  P = warp_sum(P); PP = warp_sum(PP); cnt = warp_sum(cnt);
  int lane = tid&31, w = tid>>5;
  if (lane==0){ sm[0][w]=P; sm[1][w]=PP; sm[2][w]=cnt; }
  __syncthreads();
  if (tid==0){
    float a=0.f,c=0.f,d=0.f;
    for (int i=0;i<8;i++){ a+=sm[0][i]; c+=sm[1][i]; d+=sm[2][i]; }
    float* o = &g_part[((1*8+b)*64 + blockIdx.x)*4];
    o[0]=a; o[1]=c; o[2]=d;
    __threadfence();
    int old = atomicAdd(&g_ctr, 1);
    s_last = (old == (int)(gridDim.x*gridDim.y) - 1);
  }
  __syncthreads();
  if (s_last && tid < 8){
    int bb = tid;
    volatile float* vp = g_part;
    float S=0.f, SS=0.f, Ps=0.f, PPs=0.f, np=0.f;
    for (int i=0;i<64;i++){
      S  += vp[((0*8+bb)*64+i)*4+0];
      SS += vp[((0*8+bb)*64+i)*4+1];
      Ps += vp[((1*8+bb)*64+i)*4+0];
      PPs+= vp[((1*8+bb)*64+i)*4+1];
      np += vp[((1*8+bb)*64+i)*4+2];
    }
    float T = TOTF;
    float mm = S/T;
    float neg = T - np;
    float avg1 = Ps/np;
    float mean1 = (Ps + avg1*neg)/T;
    float var1  = (PPs + avg1*avg1*neg)/T - mean1*mean1;
    float inv1  = 1.0f/sqrtf(var1 + EPSLN);
    float s1    = sqrtf(np/T);
    float SSc = SS - S*S/T;
    float QQ  = SSc - PPs;
    float avg2  = -Ps/neg;
    float mean2 = (-Ps + avg2*np)/T;
    float var2  = (QQ + avg2*avg2*np)/T - mean2*mean2;
    float inv2  = 1.0f/sqrtf(var2 + EPSLN);
    float s2    = sqrtf(neg/T);
    float* c = &g_coef[bb*8];
    c[0]=mm; c[1]=mean1; c[2]=s1*inv1; c[3]=s1*(avg1-mean1)*inv1;
    c[4]=mean2; c[5]=s2*inv2; c[6]=s2*(avg2-mean2)*inv2;
  }
}

__global__ void k_combine23()
{
  int slot = 2 + blockIdx.x;
  int t = threadIdx.x;
  if (t < 32){
    int b = t>>2, c = t&3;
    float s=0.f;
    const float* p = &g_part[((slot*8+b)*64)*4 + c];
    for (int i=0;i<64;i++) s += p[i*4];
    g_red[(slot*8+b)*4 + c] = s;
  }
}

/* ---------------- elementwise: A1(f32), A1t, A2t, XR ---------------- */
__global__ void k_elemwise(const float4* __restrict__ x,
    const float* __restrict__ sc1p, const float* __restrict__ sc2p,
    const float* __restrict__ rcp,  const float* __restrict__ nc1p,
    const float* __restrict__ nc2p,
    float4* __restrict__ A1, float4* __restrict__ A1t,
    float4* __restrict__ A2t, float4* __restrict__ XR)
{
  int idx = blockIdx.x*blockDim.x + threadIdx.x;
  if (idx >= NELEM/4) return;
  int b = idx / (NPB/4);
  const float* cf = &g_coef[b*8];
  float m=cf[0], mean1=cf[1], g1=cf[2], c1n=cf[3], mean2=cf[4], g2=cf[5], c2n=cf[6];
  float sc1=sc1p[0], sc2=sc2p[0], rc=rcp[0], nc1=nc1p[0], nc2=nc2p[0];
  float4 xv = x[idx];
  float xi[4] = {xv.x, xv.y, xv.z, xv.w};
  float o1[4], o2[4], o3[4];
  #pragma unroll
  for (int k=0;k<4;k++){
    float xc = xi[k]-m;
    float x1n, x2n, v1, v2;
    if (xc > 0.f){ x1n=(xc-mean1)*g1; x2n=c2n; v1=sc1*xc+x1n; v2=x2n; }
    else         { x1n=c1n; x2n=(xc-mean2)*g2; v1=x1n; v2=sc2*xc+x2n; }
    o1[k]=v1; o2[k]=v2; o3[k]=0.5f*(nc1*x1n+nc2*x2n)+rc*xc;
  }
  A1 [idx]=make_float4(o1[0],o1[1],o1[2],o1[3]);
  A1t[idx]=make_float4(__uint_as_float(f2tf(o1[0])),__uint_as_float(f2tf(o1[1])),
                       __uint_as_float(f2tf(o1[2])),__uint_as_float(f2tf(o1[3])));
  A2t[idx]=make_float4(__uint_as_float(f2tf(o2[0])),__uint_as_float(f2tf(o2[1])),
                       __uint_as_float(f2tf(o2[2])),__uint_as_float(f2tf(o2[3])));
  XR [idx]=make_float4(o3[0],o3[1],o3[2],o3[3]);
}

/* ---------------- weight transpose + tf32: [oc][ic][9]->[tap][ic][oc] ----- */
__global__ void k_wt(const float* __restrict__ w0, const float* __restrict__ w1,
                     const float* __restrict__ w2, const float* __restrict__ w3)
{
  int idx = blockIdx.x*blockDim.x + threadIdx.x;
  if (idx >= 4*9*Cc*Cc) return;
  int w   = idx / (9*Cc*Cc);
  int rem = idx - w*(9*Cc*Cc);
  int tap = rem / (Cc*Cc);
  int rem2= rem - tap*(Cc*Cc);
  int ic  = rem2 / Cc;
  int oc  = rem2 - ic*Cc;
  const float* src = (w==0)?w0:(w==1)?w1:(w==2)?w2:w3;
  float v = src[((size_t)oc*Cc + ic)*9 + tap];
  g_WT[idx] = __uint_as_float(f2tf(v));
}

/* ---------------- conv via mma.sync tf32, cp.async double-buffered --------
   block: 4 y-rows x 128 px x 32 oc. 8 warps = 4 rows x 2 x-halves.
   smem: Xs[2][8ic][6rows][140], Ws[2][9tap][8ic][40]  (dynamic, 76.8KB)     */
#define XS_TOT 13440
#define XS_BUF 6720
#define WS_BUF 2880

__device__ __forceinline__ void conv_load(float* Xs, float* Ws,
    const float* inb, const float* wb, int tileY, int oc0, int ic0, int p, int tid)
{
  #pragma unroll
  for (int k=0;k<6;k++){
    int t = tid + k*256;          /* 0..1535: 8 ic x 6 rows x 32 chunks */
    int ic = t / 192;
    int rem = t - ic*192;
    int r = rem >> 5, gc = rem & 31;
    int gy = tileY + r - 1;
    int ok = ((unsigned)gy < 128u);
    const float* src = inb + ((size_t)(ic0+ic)*Hh + (ok?gy:0))*Wd + gc*4;
    float* dst = Xs + (size_t)(p*8+ic)*840 + r*140 + 4 + gc*4;
    cp16(dst, src, ok);
  }
  #pragma unroll
  for (int k=0;k<3;k++){
    int t = tid + k*256;          /* 0..575: 9 tap x 8 ic x 8 chunks */
    if (t < 576){
      int tap = t / 64;
      int rem = t - tap*64;
      int ic = rem >> 3, gc = rem & 7;
      const float* src = wb + ((size_t)tap*Cc + ic0+ic)*Cc + oc0 + gc*4;
      float* dst = Ws + (size_t)(p*9+tap)*320 + ic*40 + gc*4;
      cp16(dst, src, 1);
    }
  }
}

__global__ void __launch_bounds__(256, 2)
k_conv_mma(const float* __restrict__ in, const float* __restrict__ wt,
           long wstride, float* __restrict__ out, int round_out)
{
  extern __shared__ float sm_[];
  float* Xs = sm_;
  float* Ws = sm_ + XS_TOT;
  const int b = blockIdx.z, oc0 = blockIdx.y*32, tileY = blockIdx.x*4;
  const float* inb = in + (size_t)b*NPB;
  const float* wb  = wt + (size_t)b*wstride;
  const int tid = threadIdx.x, wid = tid>>5, lane = tid&31;
  const int g = lane>>2, tig = lane&3;
  const int rowb = wid>>1, x0 = (wid&1)*64;

  for (int t = tid; t < 96; t += 256){ Xs[t*140+3]=0.f; Xs[t*140+132]=0.f; }

  float c[2][8][4];
  #pragma unroll
  for (int m=0;m<2;m++)
    #pragma unroll
    for (int j=0;j<8;j++)
      #pragma unroll
      for (int k=0;k<4;k++) c[m][j][k]=0.f;

  conv_load(Xs, Ws, inb, wb, tileY, oc0, 0, 0, tid);
  asm volatile("cp.async.commit_group;");

  for (int cc = 0; cc < 12; cc++){
    const int p = cc & 1;
    if (cc < 11){
      conv_load(Xs, Ws, inb, wb, tileY, oc0, (cc+1)*8, p^1, tid);
      asm volatile("cp.async.commit_group;");
      asm volatile("cp.async.wait_group 1;");
    } else {
      asm volatile("cp.async.wait_group 0;");
    }
    __syncthreads();

    const float* Xp = Xs + p*XS_BUF;
    const float* Wp = Ws + p*WS_BUF;
    #pragma unroll
    for (int tap = 0; tap < 9; tap++){
      const int dy = tap/3, dx = tap%3;
      const float* w0 = Wp + tap*320;
      unsigned a0[4], a1[4];
      a0[0]=__float_as_uint(w0[ tig   *40 + g   ]);
      a0[1]=__float_as_uint(w0[ tig   *40 + g+8 ]);
      a0[2]=__float_as_uint(w0[(tig+4)*40 + g   ]);
      a0[3]=__float_as_uint(w0[(tig+4)*40 + g+8 ]);
      a1[0]=__float_as_uint(w0[ tig   *40 + g+16]);
      a1[1]=__float_as_uint(w0[ tig   *40 + g+24]);
      a1[2]=__float_as_uint(w0[(tig+4)*40 + g+16]);
      a1[3]=__float_as_uint(w0[(tig+4)*40 + g+24]);
      const float* xr0 = Xp +  tig   *840 + (rowb+dy)*140;
      const float* xr1 = Xp + (tig+4)*840 + (rowb+dy)*140;
      #pragma unroll
      for (int j = 0; j < 8; j++){
        int xb = x0 + 8*j + g + dx + 3;
        unsigned b0 = __float_as_uint(xr0[xb]);
        unsigned b1 = __float_as_uint(xr1[xb]);
        mma_tf32(c[0][j], a0, b0, b1);
        mma_tf32(c[1][j], a1, b0, b1);
      }
    }
    __syncthreads();
  }

  const int y = tileY + rowb;
  #pragma unroll
  for (int m=0;m<2;m++){
    #pragma unroll
    for (int j=0;j<8;j++){
      int oc = oc0 + 16*m + g;
      int px = x0 + 8*j + 2*tig;
      size_t o0 = (((size_t)b*Cc + oc  )*Hh + y)*Wd + px;
      size_t o1 = (((size_t)b*Cc + oc+8)*Hh + y)*Wd + px;
      float v00=c[m][j][0], v01=c[m][j][1], v10=c[m][j][2], v11=c[m][j][3];
      if (round_out){
        v00=__uint_as_float(f2tf(v00)); v01=__uint_as_float(f2tf(v01));
        v10=__uint_as_float(f2tf(v10)); v11=__uint_as_float(f2tf(v11));
      }
      *(float2*)(out+o0) = make_float2(v00,v01);
      *(float2*)(out+o1) = make_float2(v10,v11);
    }
  }
}

/* ---------------- attention GEMM (4-way L-split) ---------------- */
__global__ void k_attn_gemm(const float* __restrict__ K1, const float* __restrict__ Q1,
                            float* __restrict__ attn)
{
  __shared__ float sk[16][96];
  __shared__ float sq[16][96];
  const int kidx = blockIdx.x;
  const int kh = kidx/3, kw = kidx%3;
  const int b = blockIdx.y;
  const int ls = blockIdx.z;
  const int lbeg = ls*441, lend = lbeg + 441;
  const int tid = threadIdx.x;
  const int q0 = (tid >> 4) * 6;
  const int c0 = (tid & 15) * 6;
  float acc[6][6];
  #pragma unroll
  for (int i=0;i<6;i++)
    #pragma unroll
    for (int j=0;j<6;j++) acc[i][j]=0.f;

  for (int l0 = lbeg; l0 < lend; l0 += 16){
    for (int idx = tid; idx < 1536; idx += 256){
      int c = idx >> 4; int ll = idx & 15;
      int l = l0 + ll;
      float kv=0.f, qv=0.f;
      if (l < lend){
        int ho = l/42, wo = l - ho*42;
        int pix = (3*ho+kh)*Wd + (3*wo+kw);
        size_t off = ((size_t)b*Cc + c)*HW + pix;
        kv = K1[off]; qv = Q1[off];
      }
      sk[ll][c]=kv; sq[ll][c]=qv;
    }
    __syncthreads();
    #pragma unroll
    for (int ll=0; ll<16; ll++){
      float qv[6], cv[6];
      #pragma unroll
      for (int i=0;i<6;i++) qv[i]=sq[ll][q0+i];
      #pragma unroll
      for (int j=0;j<6;j++) cv[j]=sk[ll][c0+j];
      #pragma unroll
      for (int i=0;i<6;i++)
        #pragma unroll
        for (int j=0;j<6;j++) acc[i][j] += qv[i]*cv[j];
    }
    __syncthreads();
  }
  float* op = attn + (size_t)ls*(Bn*Cc*864);
  #pragma unroll
  for (int i=0;i<6;i++)
    #pragma unroll
    for (int j=0;j<6;j++)
      op[((size_t)b*Cc + q0+i)*864 + (size_t)(c0+j)*9 + kidx] = acc[i][j];
}

/* ------- softmax: sum 4 slices, softmax, write tf32 [b][tap][c][q] -------- */
__global__ void k_softmax(float* __restrict__ attn, float* __restrict__ attnT)
{
  __shared__ float sm[8];
  __shared__ float bc;
  const int b = blockIdx.y, q = blockIdx.x, tid = threadIdx.x;
  const size_t SL = (size_t)Bn*Cc*864;
  float* row = attn + ((size_t)(b*Cc+q))*864;
  const float scale = 0.034020690871988586f;
  float mx = -1e30f;
  for (int i=tid;i<864;i+=256){
    float v = (row[i] + row[i+SL] + row[i+2*SL] + row[i+3*SL]) * scale;
    row[i] = v;
    mx = fmaxf(mx, v);
  }
  #pragma unroll
  for (int o=16;o;o>>=1) mx = fmaxf(mx, __shfl_xor_sync(0xffffffffu, mx, o));
  if ((tid&31)==0) sm[tid>>5]=mx;
  __syncthreads();
  if (tid==0){ float v=sm[0]; for(int i=1;i<8;i++) v=fmaxf(v,sm[i]); bc=v; }
  __syncthreads();
  mx = bc;
  float s=0.f;
  for (int i=tid;i<864;i+=256){ float e = expf(row[i] - mx); row[i]=e; s+=e; }
  s = warp_sum(s);
  __syncthreads();
  if ((tid&31)==0) sm[tid>>5]=s;
  __syncthreads();
  if (tid==0){ float v=0.f; for(int i=0;i<8;i++) v+=sm[i]; bc=1.0f/v; }
  __syncthreads();
  float inv = bc;
  for (int i=tid;i<864;i+=256){
    float v = row[i]*inv;
    int cch = i/9, tap = i - 9*cch;
    attnT[(((size_t)b*9 + tap)*Cc + cch)*Cc + q] = __uint_as_float(f2tf(v));
  }
}

/* ---------------- final epilogue ---------------- */
__global__ void __launch_bounds__(256)
k_final(const float* __restrict__ wf, const float* __restrict__ bias,
        const float* __restrict__ AO, const float* __restrict__ W2,
        const float* __restrict__ A1, const float* __restrict__ XR,
        float* __restrict__ out)
{
  __shared__ float yv[48][128];
  __shared__ float ws[48][96];
  const int b = blockIdx.y;
  const int pix0 = blockIdx.x * 128;
  const int tid = threadIdx.x;
  const int g = tid >> 5;
  const int s = tid & 31;

  float S1 = g_red[(2*8+b)*4+0], SS1 = g_red[(2*8+b)*4+1];
  float m1 = S1*(1.0f/TOTF);
  float inv1 = 1.0f/sqrtf(SS1*(1.0f/TOTF) - m1*m1 + EPSLN);
  float S2 = g_red[(3*8+b)*4+0], SS2 = g_red[(3*8+b)*4+1];
  float m2 = S2*(1.0f/TOTF);
  float inv2 = 1.0f/sqrtf(SS2*(1.0f/TOTF) - m2*m2 + EPSLN);

  float acc[12][4];
  #pragma unroll
  for (int j=0;j<12;j++)
    #pragma unroll
    for (int k=0;k<4;k++) acc[j][k]=0.f;

  for (int i0=0; i0<192; i0+=48){
    for (int idx=tid; idx<48*128; idx+=256){
      int ii = idx >> 7; int p = idx & 127;
      int i = i0+ii;
      float v;
      if (i < 96){
        v = (AO[((size_t)b*Cc+i)*HW + pix0+p]-m1)*inv1;
      } else {
        size_t o = ((size_t)b*Cc+(i-96))*HW + pix0+p;
        v = (W2[o]-m2)*inv2*A1[o];
      }
      yv[ii][p] = v;
    }
    for (int idx=tid; idx<48*96; idx+=256){
      int ii = idx/96, o = idx-ii*96;
      ws[ii][o] = wf[(size_t)o*192 + i0+ii];
    }
    __syncthreads();
    #pragma unroll 4
    for (int ii=0; ii<48; ii++){
      float4 v = *(const float4*)&yv[ii][s*4];
      float4 w0 = *(const float4*)&ws[ii][g*12];
      float4 w1 = *(const float4*)&ws[ii][g*12+4];
      float4 w2 = *(const float4*)&ws[ii][g*12+8];
      float wv[12] = {w0.x,w0.y,w0.z,w0.w, w1.x,w1.y,w1.z,w1.w, w2.x,w2.y,w2.z,w2.w};
      #pragma unroll
      for (int j=0;j<12;j++){
        acc[j][0] += wv[j]*v.x; acc[j][1] += wv[j]*v.y;
        acc[j][2] += wv[j]*v.z; acc[j][3] += wv[j]*v.w;
      }
    }
    __syncthreads();
  }
  #pragma unroll
  for (int j=0;j<12;j++){
    int o = g*12+j;
    size_t off = ((size_t)b*Cc+o)*HW + pix0 + s*4;
    float bb = bias[o];
    float4 xr = *(const float4*)(XR+off);
    float4 ov = make_float4(xr.x+bb+acc[j][0], xr.y+bb+acc[j][1],
                            xr.z+bb+acc[j][2], xr.w+bb+acc[j][3]);
    *(float4*)(out+off) = ov;
  }
}

/* ---------------- host ---------------- */
extern "C" void kernel_launch(void* const* d_in, const int* in_sizes, int n_in,
                              void* d_out, int out_size)
{
  const float* x    = (const float*)d_in[0];
  const float* wc2  = (const float*)d_in[1];
  const float* aw1  = (const float*)d_in[2];
  const float* aw2  = (const float*)d_in[3];
  const float* aw3  = (const float*)d_in[4];
  const float* wf   = (const float*)d_in[5];
  const float* bf   = (const float*)d_in[6];
  const float* sc1  = (const float*)d_in[7];
  const float* sc2  = (const float*)d_in[8];
  const float* rc   = (const float*)d_in[9];
  const float* nc1  = (const float*)d_in[10];
  const float* nc2  = (const float*)d_in[11];

  float *pA1,*pA1t,*pA2t,*pXR,*pK1,*pQ1,*pV,*pW2,*pAO,*pATTN,*pATTNT,*pWT;
  cudaGetSymbolAddress((void**)&pA1,  g_bA1);
  cudaGetSymbolAddress((void**)&pA1t, g_bA1t);
  cudaGetSymbolAddress((void**)&pA2t, g_bA2t);
  cudaGetSymbolAddress((void**)&pXR,  g_bXR);
  cudaGetSymbolAddress((void**)&pK1,  g_bK1);
  cudaGetSymbolAddress((void**)&pQ1,  g_bQ1);
  cudaGetSymbolAddress((void**)&pV ,  g_bV );
  cudaGetSymbolAddress((void**)&pW2,  g_bW2);
  cudaGetSymbolAddress((void**)&pAO,  g_bAO);
  cudaGetSymbolAddress((void**)&pATTN, g_ATTN);
  cudaGetSymbolAddress((void**)&pATTNT, g_ATTNT);
  cudaGetSymbolAddress((void**)&pWT, g_WT);

  static int smem_set = 0;
  if (!smem_set){
    cudaFuncSetAttribute(k_conv_mma, cudaFuncAttributeMaxDynamicSharedMemorySize,
                         (XS_TOT + 2*WS_BUF)*4);
    smem_set = 1;
  }
  const int CONV_SMEM = (XS_TOT + 2*WS_BUF)*4;   /* 76800 B */
  const long WSTRIDE = 9L*Cc*Cc;

  k_wt<<<(4*9*Cc*Cc+255)/256,256>>>(aw1, aw2, aw3, wc2);
  k_reduce_ss <<<dim3(64,8),256>>>(x, 0);
  k_reduce_pos<<<dim3(64,8),256>>>(x);
  k_elemwise<<<NELEM/4/256,256>>>((const float4*)x, sc1,sc2,rc,nc1,nc2,
                                  (float4*)pA1,(float4*)pA1t,(float4*)pA2t,(float4*)pXR);

  k_conv_mma<<<dim3(32,3,8),256,CONV_SMEM>>>(pA1t, pWT + 0*WSTRIDE, 0, pK1, 0);
  k_conv_mma<<<dim3(32,3,8),256,CONV_SMEM>>>(pA2t, pWT + 1*WSTRIDE, 0, pQ1, 0);
  k_conv_mma<<<dim3(32,3,8),256,CONV_SMEM>>>(pA1t, pWT + 2*WSTRIDE, 0, pV , 1);
  k_conv_mma<<<dim3(32,3,8),256,CONV_SMEM>>>(pA2t, pWT + 3*WSTRIDE, 0, pW2, 0);

  k_attn_gemm<<<dim3(9,8,4),256>>>(pK1, pQ1, pATTN);
  k_softmax  <<<dim3(96,8),256>>>(pATTN, pATTNT);

  k_conv_mma<<<dim3(32,3,8),256,CONV_SMEM>>>(pV, pATTNT, WSTRIDE, pAO, 0);

  k_reduce_ss<<<dim3(64,8),256>>>(pAO, 2);
  k_reduce_ss<<<dim3(64,8),256>>>(pW2, 3);
  k_combine23<<<2,32>>>();
  k_final<<<dim3(HW/128,8),256>>>(wf, bf, pAO, pW2, pA1, pXR, (float*)d_out);
}

// round 7
// speedup vs baseline: 3.7529x; 1.0299x over previous
#include <cuda_runtime.h>
#include <math.h>

#define Bn 8
#define Cc 96
#define Hh 128
#define Wd 128
#define HW (Hh*Wd)
#define NPB (Cc*HW)
#define NELEM (Bn*NPB)
#define TOTF 1572864.0f
#define EPSLN 1e-5f
#define NBE (NELEM/4/256)      /* elemwise blocks: 12288 */
#define NWT (4*9*Cc*Cc)        /* wt elements: 331776    */

/* ---------------- scratch (device globals; no allocation) ---------------- */
__device__ float4 g_bA1 [NELEM/4];
__device__ float4 g_bA1t[NELEM/4];
__device__ float4 g_bA2t[NELEM/4];
__device__ float4 g_bXR [NELEM/4];
__device__ float4 g_bK1 [NELEM/4];
__device__ float4 g_bQ1 [NELEM/4];
__device__ float4 g_bV  [NELEM/4];
__device__ float4 g_bW2 [NELEM/4];
__device__ float4 g_bAO [NELEM/4];
__device__ float  g_ATTN [4*Bn*Cc*864];
__device__ float  g_ATTNT[Bn*9*Cc*Cc];
__device__ float  g_WT[NWT];
__device__ float  g_part[4*8*96*4];   /* [slot][b][block<=96][comp] */
__device__ float  g_red [4*8*4];
__device__ float  g_coef[8*8];
__device__ int    g_ctr;

/* ---------------- helpers ---------------- */
__device__ __forceinline__ float warp_sum(float v){
  #pragma unroll
  for (int o=16;o;o>>=1) v += __shfl_xor_sync(0xffffffffu, v, o);
  return v;
}
__device__ __forceinline__ unsigned f2tf(float f){
  unsigned r; asm("cvt.rna.tf32.f32 %0, %1;" : "=r"(r) : "f"(f)); return r;
}
__device__ __forceinline__ void mma_tf32(float c[4], const unsigned a[4],
                                         unsigned b0, unsigned b1){
  asm volatile("mma.sync.aligned.m16n8k8.row.col.f32.tf32.tf32.f32 "
               "{%0,%1,%2,%3},{%4,%5,%6,%7},{%8,%9},{%0,%1,%2,%3};"
               : "+f"(c[0]),"+f"(c[1]),"+f"(c[2]),"+f"(c[3])
               : "r"(a[0]),"r"(a[1]),"r"(a[2]),"r"(a[3]),"r"(b0),"r"(b1));
}
__device__ __forceinline__ void cp16(float* dst, const float* src, int ok){
  unsigned d = (unsigned)__cvta_generic_to_shared(dst);
  asm volatile("cp.async.ca.shared.global [%0], [%1], 16, %2;"
               :: "r"(d), "l"(src), "r"(ok?16:0));
}

/* ---------------- stage 1: sum/sumsq of x (64-block partials) ------------- */
__global__ void k_reduce_ss(const float* __restrict__ in)
{
  __shared__ float sm[2][8];
  int b = blockIdx.y;
  if (blockIdx.x==0 && b==0 && threadIdx.x==0) g_ctr = 0;
  const float4* p = (const float4*)in + (size_t)b*(NPB/4);
  float s=0.f, ss=0.f;
  for (int i = blockIdx.x*blockDim.x + threadIdx.x; i < NPB/4; i += gridDim.x*blockDim.x){
    float4 v = p[i];
    s  += (v.x+v.y)+(v.z+v.w);
    ss += v.x*v.x + v.y*v.y + v.z*v.z + v.w*v.w;
  }
  s = warp_sum(s); ss = warp_sum(ss);
  int lane = threadIdx.x&31, w = threadIdx.x>>5;
  if (lane==0){ sm[0][w]=s; sm[1][w]=ss; }
  __syncthreads();
  if (threadIdx.x==0){
    float a=0.f,c=0.f;
    for (int i=0;i<8;i++){ a+=sm[0][i]; c+=sm[1][i]; }
    float* o = &g_part[((0*8+b)*96 + blockIdx.x)*4];
    o[0]=a; o[1]=c;
  }
}

/* ---------------- stage 2: pos-stats; last block emits coefficients ------ */
__global__ void k_reduce_pos(const float* __restrict__ in)
{
  __shared__ float sm[3][8];
  __shared__ float s_mu;
  __shared__ int   s_last;
  int b = blockIdx.y;
  int tid = threadIdx.x;
  if (tid==0){
    float S=0.f;
    const float* pp = &g_part[((0*8+b)*96)*4];
    for (int i=0;i<64;i++) S += pp[i*4];
    s_mu = S*(1.0f/TOTF);
  }
  __syncthreads();
  float m = s_mu;
  const float4* p = (const float4*)in + (size_t)b*(NPB/4);
  float P=0.f, PP=0.f, cnt=0.f;
  for (int i = blockIdx.x*blockDim.x + tid; i < NPB/4; i += gridDim.x*blockDim.x){
    float4 v = p[i];
    float a;
    a=v.x-m; if(a>0.f){P+=a;PP+=a*a;cnt+=1.f;}
    a=v.y-m; if(a>0.f){P+=a;PP+=a*a;cnt+=1.f;}
    a=v.z-m; if(a>0.f){P+=a;PP+=a*a;cnt+=1.f;}
    a=v.w-m; if(a>0.f){P+=a;PP+=a*a;cnt+=1.f;}
  }
  P = warp_sum(P); PP = warp_sum(PP); cnt = warp_sum(cnt);
  int lane = tid&31, w = tid>>5;
  if (lane==0){ sm[0][w]=P; sm[1][w]=PP; sm[2][w]=cnt; }
  __syncthreads();
  if (tid==0){
    float a=0.f,c=0.f,d=0.f;
    for (int i=0;i<8;i++){ a+=sm[0][i]; c+=sm[1][i]; d+=sm[2][i]; }
    float* o = &g_part[((1*8+b)*96 + blockIdx.x)*4];
    o[0]=a; o[1]=c; o[2]=d;
    __threadfence();
    int old = atomicAdd(&g_ctr, 1);
    s_last = (old == (int)(gridDim.x*gridDim.y) - 1);
  }
  __syncthreads();
  if (s_last && tid < 8){
    int bb = tid;
    volatile float* vp = g_part;
    float S=0.f, SS=0.f, Ps=0.f, PPs=0.f, np=0.f;
    for (int i=0;i<64;i++){
      S  += vp[((0*8+bb)*96+i)*4+0];
      SS += vp[((0*8+bb)*96+i)*4+1];
      Ps += vp[((1*8+bb)*96+i)*4+0];
      PPs+= vp[((1*8+bb)*96+i)*4+1];
      np += vp[((1*8+bb)*96+i)*4+2];
    }
    float T = TOTF;
    float mm = S/T;
    float neg = T - np;
    float avg1 = Ps/np;
    float mean1 = (Ps + avg1*neg)/T;
    float var1  = (PPs + avg1*avg1*neg)/T - mean1*mean1;
    float inv1  = 1.0f/sqrtf(var1 + EPSLN);
    float s1    = sqrtf(np/T);
    float SSc = SS - S*S/T;
    float QQ  = SSc - PPs;
    float avg2  = -Ps/neg;
    float mean2 = (-Ps + avg2*np)/T;
    float var2  = (QQ + avg2*avg2*np)/T - mean2*mean2;
    float inv2  = 1.0f/sqrtf(var2 + EPSLN);
    float s2    = sqrtf(neg/T);
    float* c = &g_coef[bb*8];
    c[0]=mm; c[1]=mean1; c[2]=s1*inv1; c[3]=s1*(avg1-mean1)*inv1;
    c[4]=mean2; c[5]=s2*inv2; c[6]=s2*(avg2-mean2)*inv2;
  }
}

/* ------ elementwise (A1,A1t,A2t,XR) + weight-transpose tail blocks ------- */
__global__ void k_elemwise(const float4* __restrict__ x,
    const float* __restrict__ sc1p, const float* __restrict__ sc2p,
    const float* __restrict__ rcp,  const float* __restrict__ nc1p,
    const float* __restrict__ nc2p,
    float4* __restrict__ A1, float4* __restrict__ A1t,
    float4* __restrict__ A2t, float4* __restrict__ XR,
    const float* __restrict__ w0, const float* __restrict__ w1,
    const float* __restrict__ w2, const float* __restrict__ w3)
{
  if (blockIdx.x >= NBE){
    int idx = (blockIdx.x - NBE)*256 + threadIdx.x;
    if (idx < NWT){
      int w   = idx / (9*Cc*Cc);
      int rem = idx - w*(9*Cc*Cc);
      int tap = rem / (Cc*Cc);
      int rem2= rem - tap*(Cc*Cc);
      int ic  = rem2 / Cc;
      int oc  = rem2 - ic*Cc;
      const float* src = (w==0)?w0:(w==1)?w1:(w==2)?w2:w3;
      float v = src[((size_t)oc*Cc + ic)*9 + tap];
      g_WT[idx] = __uint_as_float(f2tf(v));
    }
    return;
  }
  int idx = blockIdx.x*blockDim.x + threadIdx.x;
  int b = idx / (NPB/4);
  const float* cf = &g_coef[b*8];
  float m=cf[0], mean1=cf[1], g1=cf[2], c1n=cf[3], mean2=cf[4], g2=cf[5], c2n=cf[6];
  float sc1=sc1p[0], sc2=sc2p[0], rc=rcp[0], nc1=nc1p[0], nc2=nc2p[0];
  float4 xv = x[idx];
  float xi[4] = {xv.x, xv.y, xv.z, xv.w};
  float o1[4], o2[4], o3[4];
  #pragma unroll
  for (int k=0;k<4;k++){
    float xc = xi[k]-m;
    float x1n, x2n, v1, v2;
    if (xc > 0.f){ x1n=(xc-mean1)*g1; x2n=c2n; v1=sc1*xc+x1n; v2=x2n; }
    else         { x1n=c1n; x2n=(xc-mean2)*g2; v1=x1n; v2=sc2*xc+x2n; }
    o1[k]=v1; o2[k]=v2; o3[k]=0.5f*(nc1*x1n+nc2*x2n)+rc*xc;
  }
  A1 [idx]=make_float4(o1[0],o1[1],o1[2],o1[3]);
  A1t[idx]=make_float4(__uint_as_float(f2tf(o1[0])),__uint_as_float(f2tf(o1[1])),
                       __uint_as_float(f2tf(o1[2])),__uint_as_float(f2tf(o1[3])));
  A2t[idx]=make_float4(__uint_as_float(f2tf(o2[0])),__uint_as_float(f2tf(o2[1])),
                       __uint_as_float(f2tf(o2[2])),__uint_as_float(f2tf(o2[3])));
  XR [idx]=make_float4(o3[0],o3[1],o3[2],o3[3]);
}

/* ---------------- conv via mma.sync tf32, cp.async double-buffered --------
   block: 4 y-rows x 128 px x 32 oc. 8 warps = 4 rows x 2 x-halves.
   stat_slot>=0: fused block-partial sum/sumsq of outputs into g_part.       */
#define XS_TOT 13440
#define XS_BUF 6720
#define WS_BUF 2880

__device__ __forceinline__ void conv_load(float* Xs, float* Ws,
    const float* inb, const float* wb, int tileY, int oc0, int ic0, int p, int tid)
{
  #pragma unroll
  for (int k=0;k<6;k++){
    int t = tid + k*256;
    int ic = t / 192;
    int rem = t - ic*192;
    int r = rem >> 5, gc = rem & 31;
    int gy = tileY + r - 1;
    int ok = ((unsigned)gy < 128u);
    const float* src = inb + ((size_t)(ic0+ic)*Hh + (ok?gy:0))*Wd + gc*4;
    float* dst = Xs + (size_t)(p*8+ic)*840 + r*140 + 4 + gc*4;
    cp16(dst, src, ok);
  }
  #pragma unroll
  for (int k=0;k<3;k++){
    int t = tid + k*256;
    if (t < 576){
      int tap = t / 64;
      int rem = t - tap*64;
      int ic = rem >> 3, gc = rem & 7;
      const float* src = wb + ((size_t)tap*Cc + ic0+ic)*Cc + oc0 + gc*4;
      float* dst = Ws + (size_t)(p*9+tap)*320 + ic*40 + gc*4;
      cp16(dst, src, 1);
    }
  }
}

__global__ void __launch_bounds__(256, 2)
k_conv_mma(const float* __restrict__ in, const float* __restrict__ wt,
           long wstride, float* __restrict__ out, int round_out, int stat_slot)
{
  extern __shared__ float sm_[];
  float* Xs = sm_;
  float* Ws = sm_ + XS_TOT;
  __shared__ float s_red[8][2];
  const int b = blockIdx.z, oc0 = blockIdx.y*32, tileY = blockIdx.x*4;
  const float* inb = in + (size_t)b*NPB;
  const float* wb  = wt + (size_t)b*wstride;
  const int tid = threadIdx.x, wid = tid>>5, lane = tid&31;
  const int g = lane>>2, tig = lane&3;
  const int rowb = wid>>1, x0 = (wid&1)*64;

  for (int t = tid; t < 96; t += 256){ Xs[t*140+3]=0.f; Xs[t*140+132]=0.f; }

  float c[2][8][4];
  #pragma unroll
  for (int m=0;m<2;m++)
    #pragma unroll
    for (int j=0;j<8;j++)
      #pragma unroll
      for (int k=0;k<4;k++) c[m][j][k]=0.f;

  conv_load(Xs, Ws, inb, wb, tileY, oc0, 0, 0, tid);
  asm volatile("cp.async.commit_group;");

  for (int cc = 0; cc < 12; cc++){
    const int p = cc & 1;
    if (cc < 11){
      conv_load(Xs, Ws, inb, wb, tileY, oc0, (cc+1)*8, p^1, tid);
      asm volatile("cp.async.commit_group;");
      asm volatile("cp.async.wait_group 1;");
    } else {
      asm volatile("cp.async.wait_group 0;");
    }
    __syncthreads();

    const float* Xp = Xs + p*XS_BUF;
    const float* Wp = Ws + p*WS_BUF;
    #pragma unroll
    for (int tap = 0; tap < 9; tap++){
      const int dy = tap/3, dx = tap%3;
      const float* w0 = Wp + tap*320;
      unsigned a0[4], a1[4];
      a0[0]=__float_as_uint(w0[ tig   *40 + g   ]);
      a0[1]=__float_as_uint(w0[ tig   *40 + g+8 ]);
      a0[2]=__float_as_uint(w0[(tig+4)*40 + g   ]);
      a0[3]=__float_as_uint(w0[(tig+4)*40 + g+8 ]);
      a1[0]=__float_as_uint(w0[ tig   *40 + g+16]);
      a1[1]=__float_as_uint(w0[ tig   *40 + g+24]);
      a1[2]=__float_as_uint(w0[(tig+4)*40 + g+16]);
      a1[3]=__float_as_uint(w0[(tig+4)*40 + g+24]);
      const float* xr0 = Xp +  tig   *840 + (rowb+dy)*140;
      const float* xr1 = Xp + (tig+4)*840 + (rowb+dy)*140;
      #pragma unroll
      for (int j = 0; j < 8; j++){
        int xb = x0 + 8*j + g + dx + 3;
        unsigned b0 = __float_as_uint(xr0[xb]);
        unsigned b1 = __float_as_uint(xr1[xb]);
        mma_tf32(c[0][j], a0, b0, b1);
        mma_tf32(c[1][j], a1, b0, b1);
      }
    }
    __syncthreads();
  }

  const int y = tileY + rowb;
  float psum=0.f, psq=0.f;
  #pragma unroll
  for (int m=0;m<2;m++){
    #pragma unroll
    for (int j=0;j<8;j++){
      int oc = oc0 + 16*m + g;
      int px = x0 + 8*j + 2*tig;
      size_t o0 = (((size_t)b*Cc + oc  )*Hh + y)*Wd + px;
      size_t o1 = (((size_t)b*Cc + oc+8)*Hh + y)*Wd + px;
      float v00=c[m][j][0], v01=c[m][j][1], v10=c[m][j][2], v11=c[m][j][3];
      if (round_out){
        v00=__uint_as_float(f2tf(v00)); v01=__uint_as_float(f2tf(v01));
        v10=__uint_as_float(f2tf(v10)); v11=__uint_as_float(f2tf(v11));
      }
      psum += (v00+v01)+(v10+v11);
      psq  += v00*v00 + v01*v01 + v10*v10 + v11*v11;
      *(float2*)(out+o0) = make_float2(v00,v01);
      *(float2*)(out+o1) = make_float2(v10,v11);
    }
  }
  if (stat_slot >= 0){
    psum = warp_sum(psum); psq = warp_sum(psq);
    if (lane==0){ s_red[wid][0]=psum; s_red[wid][1]=psq; }
    __syncthreads();
    if (tid==0){
      float a=0.f, q=0.f;
      for (int i=0;i<8;i++){ a+=s_red[i][0]; q+=s_red[i][1]; }
      float* o = &g_part[((stat_slot*8+b)*96 + blockIdx.x*3 + blockIdx.y)*4];
      o[0]=a; o[1]=q;
    }
  }
}

/* ---------------- attention GEMM (4-way L-split) ---------------- */
__global__ void k_attn_gemm(const float* __restrict__ K1, const float* __restrict__ Q1,
                            float* __restrict__ attn)
{
  __shared__ float sk[16][96];
  __shared__ float sq[16][96];
  const int kidx = blockIdx.x;
  const int kh = kidx/3, kw = kidx%3;
  const int b = blockIdx.y;
  const int ls = blockIdx.z;
  const int lbeg = ls*441, lend = lbeg + 441;
  const int tid = threadIdx.x;
  const int q0 = (tid >> 4) * 6;
  const int c0 = (tid & 15) * 6;
  float acc[6][6];
  #pragma unroll
  for (int i=0;i<6;i++)
    #pragma unroll
    for (int j=0;j<6;j++) acc[i][j]=0.f;

  for (int l0 = lbeg; l0 < lend; l0 += 16){
    for (int idx = tid; idx < 1536; idx += 256){
      int c = idx >> 4; int ll = idx & 15;
      int l = l0 + ll;
      float kv=0.f, qv=0.f;
      if (l < lend){
        int ho = l/42, wo = l - ho*42;
        int pix = (3*ho+kh)*Wd + (3*wo+kw);
        size_t off = ((size_t)b*Cc + c)*HW + pix;
        kv = K1[off]; qv = Q1[off];
      }
      sk[ll][c]=kv; sq[ll][c]=qv;
    }
    __syncthreads();
    #pragma unroll
    for (int ll=0; ll<16; ll++){
      float qv[6], cv[6];
      #pragma unroll
      for (int i=0;i<6;i++) qv[i]=sq[ll][q0+i];
      #pragma unroll
      for (int j=0;j<6;j++) cv[j]=sk[ll][c0+j];
      #pragma unroll
      for (int i=0;i<6;i++)
        #pragma unroll
        for (int j=0;j<6;j++) acc[i][j] += qv[i]*cv[j];
    }
    __syncthreads();
  }
  float* op = attn + (size_t)ls*(Bn*Cc*864);
  #pragma unroll
  for (int i=0;i<6;i++)
    #pragma unroll
    for (int j=0;j<6;j++)
      op[((size_t)b*Cc + q0+i)*864 + (size_t)(c0+j)*9 + kidx] = acc[i][j];
}

/* ------- softmax: sum 4 slices, softmax, write tf32 [b][tap][c][q] -------- */
__global__ void k_softmax(float* __restrict__ attn, float* __restrict__ attnT)
{
  __shared__ float sm[8];
  __shared__ float bc;
  const int b = blockIdx.y, q = blockIdx.x, tid = threadIdx.x;
  const size_t SL = (size_t)Bn*Cc*864;
  float* row = attn + ((size_t)(b*Cc+q))*864;
  const float scale = 0.034020690871988586f;
  float mx = -1e30f;
  for (int i=tid;i<864;i+=256){
    float v = (row[i] + row[i+SL] + row[i+2*SL] + row[i+3*SL]) * scale;
    row[i] = v;
    mx = fmaxf(mx, v);
  }
  #pragma unroll
  for (int o=16;o;o>>=1) mx = fmaxf(mx, __shfl_xor_sync(0xffffffffu, mx, o));
  if ((tid&31)==0) sm[tid>>5]=mx;
  __syncthreads();
  if (tid==0){ float v=sm[0]; for(int i=1;i<8;i++) v=fmaxf(v,sm[i]); bc=v; }
  __syncthreads();
  mx = bc;
  float s=0.f;
  for (int i=tid;i<864;i+=256){ float e = expf(row[i] - mx); row[i]=e; s+=e; }
  s = warp_sum(s);
  __syncthreads();
  if ((tid&31)==0) sm[tid>>5]=s;
  __syncthreads();
  if (tid==0){ float v=0.f; for(int i=0;i<8;i++) v+=sm[i]; bc=1.0f/v; }
  __syncthreads();
  float inv = bc;
  for (int i=tid;i<864;i+=256){
    float v = row[i]*inv;
    int cch = i/9, tap = i - 9*cch;
    attnT[(((size_t)b*9 + tap)*Cc + cch)*Cc + q] = __uint_as_float(f2tf(v));
  }
}

/* ----- combine conv-fused partials (96 blocks) into g_red slots 2,3 ------ */
__global__ void k_combine23()
{
  int slot = 2 + blockIdx.x;
  int t = threadIdx.x;
  if (t < 16){
    int b = t>>1, c = t&1;
    float s=0.f;
    const float* p = &g_part[((slot*8+b)*96)*4 + c];
    for (int i=0;i<96;i++) s += p[i*4];
    g_red[(slot*8+b)*4 + c] = s;
  }
}

/* ---------------- final epilogue ---------------- */
__global__ void __launch_bounds__(256)
k_final(const float* __restrict__ wf, const float* __restrict__ bias,
        const float* __restrict__ AO, const float* __restrict__ W2,
        const float* __restrict__ A1, const float* __restrict__ XR,
        float* __restrict__ out)
{
  __shared__ float yv[48][128];
  __shared__ float ws[48][96];
  const int b = blockIdx.y;
  const int pix0 = blockIdx.x * 128;
  const int tid = threadIdx.x;
  const int g = tid >> 5;
  const int s = tid & 31;

  float S1 = g_red[(2*8+b)*4+0], SS1 = g_red[(2*8+b)*4+1];
  float m1 = S1*(1.0f/TOTF);
  float inv1 = 1.0f/sqrtf(SS1*(1.0f/TOTF) - m1*m1 + EPSLN);
  float S2 = g_red[(3*8+b)*4+0], SS2 = g_red[(3*8+b)*4+1];
  float m2 = S2*(1.0f/TOTF);
  float inv2 = 1.0f/sqrtf(SS2*(1.0f/TOTF) - m2*m2 + EPSLN);

  float acc[12][4];
  #pragma unroll
  for (int j=0;j<12;j++)
    #pragma unroll
    for (int k=0;k<4;k++) acc[j][k]=0.f;

  for (int i0=0; i0<192; i0+=48){
    for (int idx=tid; idx<48*128; idx+=256){
      int ii = idx >> 7; int p = idx & 127;
      int i = i0+ii;
      float v;
      if (i < 96){
        v = (AO[((size_t)b*Cc+i)*HW + pix0+p]-m1)*inv1;
      } else {
        size_t o = ((size_t)b*Cc+(i-96))*HW + pix0+p;
        v = (W2[o]-m2)*inv2*A1[o];
      }
      yv[ii][p] = v;
    }
    for (int idx=tid; idx<48*96; idx+=256){
      int ii = idx/96, o = idx-ii*96;
      ws[ii][o] = wf[(size_t)o*192 + i0+ii];
    }
    __syncthreads();
    #pragma unroll 4
    for (int ii=0; ii<48; ii++){
      float4 v = *(const float4*)&yv[ii][s*4];
      float4 w0 = *(const float4*)&ws[ii][g*12];
      float4 w1 = *(const float4*)&ws[ii][g*12+4];
      float4 w2 = *(const float4*)&ws[ii][g*12+8];
      float wv[12] = {w0.x,w0.y,w0.z,w0.w, w1.x,w1.y,w1.z,w1.w, w2.x,w2.y,w2.z,w2.w};
      #pragma unroll
      for (int j=0;j<12;j++){
        acc[j][0] += wv[j]*v.x; acc[j][1] += wv[j]*v.y;
        acc[j][2] += wv[j]*v.z; acc[j][3] += wv[j]*v.w;
      }
    }
    __syncthreads();
  }
  #pragma unroll
  for (int j=0;j<12;j++){
    int o = g*12+j;
    size_t off = ((size_t)b*Cc+o)*HW + pix0 + s*4;
    float bb = bias[o];
    float4 xr = *(const float4*)(XR+off);
    float4 ov = make_float4(xr.x+bb+acc[j][0], xr.y+bb+acc[j][1],
                            xr.z+bb+acc[j][2], xr.w+bb+acc[j][3]);
    *(float4*)(out+off) = ov;
  }
}

/* ---------------- host ---------------- */
extern "C" void kernel_launch(void* const* d_in, const int* in_sizes, int n_in,
                              void* d_out, int out_size)
{
  const float* x    = (const float*)d_in[0];
  const float* wc2  = (const float*)d_in[1];
  const float* aw1  = (const float*)d_in[2];
  const float* aw2  = (const float*)d_in[3];
  const float* aw3  = (const float*)d_in[4];
  const float* wf   = (const float*)d_in[5];
  const float* bf   = (const float*)d_in[6];
  const float* sc1  = (const float*)d_in[7];
  const float* sc2  = (const float*)d_in[8];
  const float* rc   = (const float*)d_in[9];
  const float* nc1  = (const float*)d_in[10];
  const float* nc2  = (const float*)d_in[11];

  float *pA1,*pA1t,*pA2t,*pXR,*pK1,*pQ1,*pV,*pW2,*pAO,*pATTN,*pATTNT,*pWT;
  cudaGetSymbolAddress((void**)&pA1,  g_bA1);
  cudaGetSymbolAddress((void**)&pA1t, g_bA1t);
  cudaGetSymbolAddress((void**)&pA2t, g_bA2t);
  cudaGetSymbolAddress((void**)&pXR,  g_bXR);
  cudaGetSymbolAddress((void**)&pK1,  g_bK1);
  cudaGetSymbolAddress((void**)&pQ1,  g_bQ1);
  cudaGetSymbolAddress((void**)&pV ,  g_bV );
  cudaGetSymbolAddress((void**)&pW2,  g_bW2);
  cudaGetSymbolAddress((void**)&pAO,  g_bAO);
  cudaGetSymbolAddress((void**)&pATTN, g_ATTN);
  cudaGetSymbolAddress((void**)&pATTNT, g_ATTNT);
  cudaGetSymbolAddress((void**)&pWT, g_WT);

  static int smem_set = 0;
  if (!smem_set){
    cudaFuncSetAttribute(k_conv_mma, cudaFuncAttributeMaxDynamicSharedMemorySize,
                         (XS_TOT + 2*WS_BUF)*4);
    smem_set = 1;
  }
  const int CONV_SMEM = (XS_TOT + 2*WS_BUF)*4;   /* 76800 B */
  const long WSTRIDE = 9L*Cc*Cc;
  const int NB_TOT = NBE + (NWT + 255)/256;

  /* launch order matters: #4 (first conv) is what ncu captures */
  k_reduce_ss <<<dim3(64,8),256>>>(x);                                   /* 1 */
  k_reduce_pos<<<dim3(64,8),256>>>(x);                                   /* 2 */
  k_elemwise<<<NB_TOT,256>>>((const float4*)x, sc1,sc2,rc,nc1,nc2,       /* 3 */
                             (float4*)pA1,(float4*)pA1t,(float4*)pA2t,(float4*)pXR,
                             aw1, aw2, aw3, wc2);
  k_conv_mma<<<dim3(32,3,8),256,CONV_SMEM>>>(pA1t, pWT+0*WSTRIDE, 0, pK1, 0, -1); /* 4: PROFILED */
  k_conv_mma<<<dim3(32,3,8),256,CONV_SMEM>>>(pA2t, pWT+1*WSTRIDE, 0, pQ1, 0, -1);
  k_conv_mma<<<dim3(32,3,8),256,CONV_SMEM>>>(pA1t, pWT+2*WSTRIDE, 0, pV , 1, -1);
  k_conv_mma<<<dim3(32,3,8),256,CONV_SMEM>>>(pA2t, pWT+3*WSTRIDE, 0, pW2, 0,  3);

  k_attn_gemm<<<dim3(9,8,4),256>>>(pK1, pQ1, pATTN);
  k_softmax  <<<dim3(96,8),256>>>(pATTN, pATTNT);

  k_conv_mma<<<dim3(32,3,8),256,CONV_SMEM>>>(pV, pATTNT, WSTRIDE, pAO, 0, 2);

  k_combine23<<<2,32>>>();
  k_final<<<dim3(HW/128,8),256>>>(wf, bf, pAO, pW2, pA1, pXR, (float*)d_out);
}

// round 10
// speedup vs baseline: 4.7005x; 1.2525x over previous
#include <cuda_runtime.h>
#include <cuda_fp16.h>
#include <math.h>

#define Bn 8
#define Cc 96
#define Hh 128
#define Wd 128
#define HW (Hh*Wd)
#define NPB (Cc*HW)
#define NELEM (Bn*NPB)
#define TOTF 1572864.0f
#define EPSLN 1e-5f
#define NBE (NELEM/4/256)          /* elemwise main blocks: 12288 */
#define NWTH (4*9*48*96)           /* packed half2 weight entries: 165888 */

/* ---------------- scratch (device globals; no allocation) ---------------- */
__device__ float4   g_bA1 [NELEM/4];     /* x1 fp32 (k_final)            */
__device__ unsigned g_bA1h[NELEM/2];     /* x1 half2 packed [cp][pix][2] */
__device__ unsigned g_bA2h[NELEM/2];     /* x2 half2 packed              */
__device__ float4   g_bXR [NELEM/4];
__device__ float4   g_bK1 [NELEM/4];
__device__ float4   g_bQ1 [NELEM/4];
__device__ float4   g_bV  [NELEM/4];     /* tf32-rounded fp32            */
__device__ float4   g_bW2 [NELEM/4];
__device__ float4   g_bAO [NELEM/4];
__device__ float    g_ATTN [4*Bn*Cc*864];
__device__ float    g_ATTNT[Bn*9*Cc*Cc];
__device__ unsigned g_WTh[NWTH];         /* fixed w half2 [w][tap][icp][oc] */
__device__ float    g_part[4*8*96*4];
__device__ float    g_red [4*8*4];
__device__ float    g_coef[8*8];
__device__ int      g_ctr;

/* ---------------- helpers ---------------- */
__device__ __forceinline__ float warp_sum(float v){
  #pragma unroll
  for (int o=16;o;o>>=1) v += __shfl_xor_sync(0xffffffffu, v, o);
  return v;
}
__device__ __forceinline__ unsigned f2tf(float f){
  unsigned r; asm("cvt.rna.tf32.f32 %0, %1;" : "=r"(r) : "f"(f)); return r;
}
__device__ __forceinline__ unsigned packh2(float lo, float hi){
  __half2 h = __halves2half2(__float2half_rn(lo), __float2half_rn(hi));
  return *(unsigned*)&h;
}
__device__ __forceinline__ void mma_tf32(float c[4], const unsigned a[4],
                                         unsigned b0, unsigned b1){
  asm volatile("mma.sync.aligned.m16n8k8.row.col.f32.tf32.tf32.f32 "
               "{%0,%1,%2,%3},{%4,%5,%6,%7},{%8,%9},{%0,%1,%2,%3};"
               : "+f"(c[0]),"+f"(c[1]),"+f"(c[2]),"+f"(c[3])
               : "r"(a[0]),"r"(a[1]),"r"(a[2]),"r"(a[3]),"r"(b0),"r"(b1));
}
__device__ __forceinline__ void mma_f16(float c[4], const unsigned a[4],
                                        unsigned b0, unsigned b1){
  asm volatile("mma.sync.aligned.m16n8k16.row.col.f32.f16.f16.f32 "
               "{%0,%1,%2,%3},{%4,%5,%6,%7},{%8,%9},{%0,%1,%2,%3};"
               : "+f"(c[0]),"+f"(c[1]),"+f"(c[2]),"+f"(c[3])
               : "r"(a[0]),"r"(a[1]),"r"(a[2]),"r"(a[3]),"r"(b0),"r"(b1));
}
__device__ __forceinline__ void cp16(void* dst, const void* src, int ok){
  unsigned d = (unsigned)__cvta_generic_to_shared(dst);
  asm volatile("cp.async.ca.shared.global [%0], [%1], 16, %2;"
               :: "r"(d), "l"(src), "r"(ok?16:0));
}

/* ---------------- stage 1: sum/sumsq of x ---------------- */
__global__ void k_reduce_ss(const float* __restrict__ in)
{
  __shared__ float sm[2][8];
  int b = blockIdx.y;
  if (blockIdx.x==0 && b==0 && threadIdx.x==0) g_ctr = 0;
  const float4* p = (const float4*)in + (size_t)b*(NPB/4);
  float s=0.f, ss=0.f;
  for (int i = blockIdx.x*blockDim.x + threadIdx.x; i < NPB/4; i += gridDim.x*blockDim.x){
    float4 v = p[i];
    s  += (v.x+v.y)+(v.z+v.w);
    ss += v.x*v.x + v.y*v.y + v.z*v.z + v.w*v.w;
  }
  s = warp_sum(s); ss = warp_sum(ss);
  int lane = threadIdx.x&31, w = threadIdx.x>>5;
  if (lane==0){ sm[0][w]=s; sm[1][w]=ss; }
  __syncthreads();
  if (threadIdx.x==0){
    float a=0.f,c=0.f;
    for (int i=0;i<8;i++){ a+=sm[0][i]; c+=sm[1][i]; }
    float* o = &g_part[((0*8+b)*96 + blockIdx.x)*4];
    o[0]=a; o[1]=c;
  }
}

/* ---------------- stage 2: pos-stats; last block emits coefficients ------ */
__global__ void k_reduce_pos(const float* __restrict__ in)
{
  __shared__ float sm[3][8];
  __shared__ float s_mu;
  __shared__ int   s_last;
  int b = blockIdx.y;
  int tid = threadIdx.x;
  if (tid==0){
    float S=0.f;
    const float* pp = &g_part[((0*8+b)*96)*4];
    for (int i=0;i<64;i++) S += pp[i*4];
    s_mu = S*(1.0f/TOTF);
  }
  __syncthreads();
  float m = s_mu;
  const float4* p = (const float4*)in + (size_t)b*(NPB/4);
  float P=0.f, PP=0.f, cnt=0.f;
  for (int i = blockIdx.x*blockDim.x + tid; i < NPB/4; i += gridDim.x*blockDim.x){
    float4 v = p[i];
    float a;
    a=v.x-m; if(a>0.f){P+=a;PP+=a*a;cnt+=1.f;}
    a=v.y-m; if(a>0.f){P+=a;PP+=a*a;cnt+=1.f;}
    a=v.z-m; if(a>0.f){P+=a;PP+=a*a;cnt+=1.f;}
    a=v.w-m; if(a>0.f){P+=a;PP+=a*a;cnt+=1.f;}
  }
  P = warp_sum(P); PP = warp_sum(PP); cnt = warp_sum(cnt);
  int lane = tid&31, w = tid>>5;
  if (lane==0){ sm[0][w]=P; sm[1][w]=PP; sm[2][w]=cnt; }
  __syncthreads();
  if (tid==0){
    float a=0.f,c=0.f,d=0.f;
    for (int i=0;i<8;i++){ a+=sm[0][i]; c+=sm[1][i]; d+=sm[2][i]; }
    float* o = &g_part[((1*8+b)*96 + blockIdx.x)*4];
    o[0]=a; o[1]=c; o[2]=d;
    __threadfence();
    int old = atomicAdd(&g_ctr, 1);
    s_last = (old == (int)(gridDim.x*gridDim.y) - 1);
  }
  __syncthreads();
  if (s_last && tid < 8){
    int bb = tid;
    volatile float* vp = g_part;
    float S=0.f, SS=0.f, Ps=0.f, PPs=0.f, np=0.f;
    for (int i=0;i<64;i++){
      S  += vp[((0*8+bb)*96+i)*4+0];
      SS += vp[((0*8+bb)*96+i)*4+1];
      Ps += vp[((1*8+bb)*96+i)*4+0];
      PPs+= vp[((1*8+bb)*96+i)*4+1];
      np += vp[((1*8+bb)*96+i)*4+2];
    }
    float T = TOTF;
    float mm = S/T;
    float neg = T - np;
    float avg1 = Ps/np;
    float mean1 = (Ps + avg1*neg)/T;
    float var1  = (PPs + avg1*avg1*neg)/T - mean1*mean1;
    float inv1  = 1.0f/sqrtf(var1 + EPSLN);
    float s1    = sqrtf(np/T);
    float SSc = SS - S*S/T;
    float QQ  = SSc - PPs;
    float avg2  = -Ps/neg;
    float mean2 = (-Ps + avg2*np)/T;
    float var2  = (QQ + avg2*avg2*np)/T - mean2*mean2;
    float inv2  = 1.0f/sqrtf(var2 + EPSLN);
    float s2    = sqrtf(neg/T);
    float* c = &g_coef[bb*8];
    c[0]=mm; c[1]=mean1; c[2]=s1*inv1; c[3]=s1*(avg1-mean1)*inv1;
    c[4]=mean2; c[5]=s2*inv2; c[6]=s2*(avg2-mean2)*inv2;
  }
}

/* ------ elementwise: A1(f32), A1h/A2h (packed half2), XR; + weight tail -- */
__global__ void k_elemwise(const float* __restrict__ x,
    const float* __restrict__ sc1p, const float* __restrict__ sc2p,
    const float* __restrict__ rcp,  const float* __restrict__ nc1p,
    const float* __restrict__ nc2p,
    float* __restrict__ A1, unsigned* __restrict__ A1h,
    unsigned* __restrict__ A2h, float* __restrict__ XR,
    const float* __restrict__ w0, const float* __restrict__ w1,
    const float* __restrict__ w2, const float* __restrict__ w3)
{
  if (blockIdx.x >= NBE){
    int idx = (blockIdx.x - NBE)*256 + threadIdx.x;
    if (idx < NWTH){
      int w   = idx / (9*48*96);
      int rem = idx - w*(9*48*96);
      int tap = rem / (48*96);
      int rem2= rem - tap*(48*96);
      int icp = rem2 / 96;
      int oc  = rem2 - icp*96;
      const float* src = (w==0)?w0:(w==1)?w1:(w==2)?w2:w3;
      float vlo = src[((size_t)oc*Cc + 2*icp  )*9 + tap];
      float vhi = src[((size_t)oc*Cc + 2*icp+1)*9 + tap];
      g_WTh[idx] = packh2(vlo, vhi);
    }
    return;
  }
  int gidx = blockIdx.x*256 + threadIdx.x;
  int p2   = gidx & 8191;            /* HW/2 */
  int rest = gidx >> 13;
  int cp   = rest % 48;
  int b    = rest / 48;
  const float* cf = &g_coef[b*8];
  float m=cf[0], mean1=cf[1], g1=cf[2], c1n=cf[3], mean2=cf[4], g2=cf[5], c2n=cf[6];
  float sc1=sc1p[0], sc2=sc2p[0], rc=rcp[0], nc1=nc1p[0], nc2=nc2p[0];
  size_t base0 = ((size_t)b*Cc + 2*cp)*HW + 2*p2;
  float2 xa = *(const float2*)(x + base0);        /* channel 2cp,   px 2p2..+1 */
  float2 xb = *(const float2*)(x + base0 + HW);   /* channel 2cp+1             */
  float xi[2][2] = {{xa.x, xa.y},{xb.x, xb.y}};
  float o1[2][2], o2[2][2], o3[2][2];
  #pragma unroll
  for (int cI=0;cI<2;cI++){
    #pragma unroll
    for (int pI=0;pI<2;pI++){
      float xc = xi[cI][pI]-m;
      float x1n, x2n, v1, v2;
      if (xc > 0.f){ x1n=(xc-mean1)*g1; x2n=c2n; v1=sc1*xc+x1n; v2=x2n; }
      else         { x1n=c1n; x2n=(xc-mean2)*g2; v1=x1n; v2=sc2*xc+x2n; }
      o1[cI][pI]=v1; o2[cI][pI]=v2; o3[cI][pI]=0.5f*(nc1*x1n+nc2*x2n)+rc*xc;
    }
  }
  *(float2*)(A1+base0)      = make_float2(o1[0][0],o1[0][1]);
  *(float2*)(A1+base0+HW)   = make_float2(o1[1][0],o1[1][1]);
  *(float2*)(XR+base0)      = make_float2(o3[0][0],o3[0][1]);
  *(float2*)(XR+base0+HW)   = make_float2(o3[1][0],o3[1][1]);
  size_t ho = (size_t)b*(NPB/2) + (size_t)cp*HW + 2*p2;
  *(uint2*)(A1h+ho) = make_uint2(packh2(o1[0][0],o1[1][0]), packh2(o1[0][1],o1[1][1]));
  *(uint2*)(A2h+ho) = make_uint2(packh2(o2[0][0],o2[1][0]), packh2(o2[0][1],o2[1][1]));
}

/* ---------------- fp16 conv (4 fixed convs): m16n8k16, cp.async DB --------
   block: 4 y-rows x 128 px x 32 oc. 6 ic-chunks of 16 (8 icp half2 rows).  */
#define HX_BUF 6720   /* uints: 8 icp x 6 rows x 140 */
#define HW_BUF 2880   /* uints: 9 tap x 8 icp x 40   */
#define CONV_SMEM ((2*HX_BUF + 2*HW_BUF)*4)   /* 76800 B */

__device__ __forceinline__ void conv_load_h(unsigned* Xs, unsigned* Ws,
    const unsigned* inb, const unsigned* wbh, int tileY, int oc0, int cc, int p, int tid)
{
  #pragma unroll
  for (int k=0;k<6;k++){
    int t = tid + k*256;              /* 1536: 8 icp x 6 rows x 32 chunks */
    int icp = t / 192;
    int rem = t - icp*192;
    int r = rem >> 5, gc = rem & 31;
    int gy = tileY + r - 1;
    int ok = ((unsigned)gy < 128u);
    const unsigned* src = inb + (size_t)(cc*8+icp)*HW + (ok?gy:0)*Wd + gc*4;
    unsigned* dst = Xs + (size_t)(p*8+icp)*840 + r*140 + 4 + gc*4;
    cp16(dst, src, ok);
  }
  #pragma unroll
  for (int k=0;k<3;k++){
    int t = tid + k*256;              /* 576: 9 tap x 8 icp x 8 chunks */
    if (t < 576){
      int tap = t / 64;
      int rem = t - tap*64;
      int icp = rem >> 3, gc = rem & 7;
      const unsigned* src = wbh + ((size_t)tap*48 + cc*8+icp)*96 + oc0 + gc*4;
      unsigned* dst = Ws + ((size_t)(p*9+tap)*8 + icp)*40 + gc*4;
      cp16(dst, src, 1);
    }
  }
}

__global__ void __launch_bounds__(256, 2)
k_conv_h(const unsigned* __restrict__ in, const unsigned* __restrict__ wbh,
         float* __restrict__ out, int round_out, int stat_slot)
{
  extern __shared__ unsigned smh_[];
  unsigned* Xs = smh_;
  unsigned* Ws = smh_ + 2*HX_BUF;
  __shared__ float s_red[8][2];
  const int b = blockIdx.z, oc0 = blockIdx.y*32, tileY = blockIdx.x*4;
  const unsigned* inb = in + (size_t)b*(NPB/2);
  const int tid = threadIdx.x, wid = tid>>5, lane = tid&31;
  const int g = lane>>2, tig = lane&3;
  const int rowb = wid>>1, x0 = (wid&1)*64;

  for (int t = tid; t < 96; t += 256){ Xs[t*140+3]=0u; Xs[t*140+132]=0u; }

  float c[2][8][4];
  #pragma unroll
  for (int m=0;m<2;m++)
    #pragma unroll
    for (int j=0;j<8;j++)
      #pragma unroll
      for (int k=0;k<4;k++) c[m][j][k]=0.f;

  conv_load_h(Xs, Ws, inb, wbh, tileY, oc0, 0, 0, tid);
  asm volatile("cp.async.commit_group;");

  for (int cc = 0; cc < 6; cc++){
    const int p = cc & 1;
    if (cc < 5){
      conv_load_h(Xs, Ws, inb, wbh, tileY, oc0, cc+1, p^1, tid);
      asm volatile("cp.async.commit_group;");
      asm volatile("cp.async.wait_group 1;");
    } else {
      asm volatile("cp.async.wait_group 0;");
    }
    __syncthreads();

    const unsigned* Xp = Xs + p*HX_BUF;
    const unsigned* Wp = Ws + p*HW_BUF;
    #pragma unroll
    for (int tap = 0; tap < 9; tap++){
      const int dy = tap/3, dx = tap%3;
      const unsigned* w0 = Wp + tap*320;
      unsigned a0[4], a1[4];
      a0[0]=w0[ tig   *40 + g   ];
      a0[1]=w0[ tig   *40 + g+8 ];
      a0[2]=w0[(tig+4)*40 + g   ];
      a0[3]=w0[(tig+4)*40 + g+8 ];
      a1[0]=w0[ tig   *40 + g+16];
      a1[1]=w0[ tig   *40 + g+24];
      a1[2]=w0[(tig+4)*40 + g+16];
      a1[3]=w0[(tig+4)*40 + g+24];
      const unsigned* xr0 = Xp +  tig   *840 + (rowb+dy)*140;
      const unsigned* xr1 = Xp + (tig+4)*840 + (rowb+dy)*140;
      #pragma unroll
      for (int j = 0; j < 8; j++){
        int xb = x0 + 8*j + g + dx + 3;
        unsigned b0 = xr0[xb];
        unsigned b1 = xr1[xb];
        mma_f16(c[0][j], a0, b0, b1);
        mma_f16(c[1][j], a1, b0, b1);
      }
    }
    __syncthreads();
  }

  const int y = tileY + rowb;
  float psum=0.f, psq=0.f;
  #pragma unroll
  for (int m=0;m<2;m++){
    #pragma unroll
    for (int j=0;j<8;j++){
      int oc = oc0 + 16*m + g;
      int px = x0 + 8*j + 2*tig;
      size_t o0 = (((size_t)b*Cc + oc  )*Hh + y)*Wd + px;
      size_t o1 = (((size_t)b*Cc + oc+8)*Hh + y)*Wd + px;
      float v00=c[m][j][0], v01=c[m][j][1], v10=c[m][j][2], v11=c[m][j][3];
      if (round_out){
        v00=__uint_as_float(f2tf(v00)); v01=__uint_as_float(f2tf(v01));
        v10=__uint_as_float(f2tf(v10)); v11=__uint_as_float(f2tf(v11));
      }
      psum += (v00+v01)+(v10+v11);
      psq  += v00*v00 + v01*v01 + v10*v10 + v11*v11;
      *(float2*)(out+o0) = make_float2(v00,v01);
      *(float2*)(out+o1) = make_float2(v10,v11);
    }
  }
  if (stat_slot >= 0){
    psum = warp_sum(psum); psq = warp_sum(psq);
    if (lane==0){ s_red[wid][0]=psum; s_red[wid][1]=psq; }
    __syncthreads();
    if (tid==0){
      float a=0.f, q=0.f;
      for (int i=0;i<8;i++){ a+=s_red[i][0]; q+=s_red[i][1]; }
      float* o = &g_part[((stat_slot*8+b)*96 + blockIdx.x*3 + blockIdx.y)*4];
      o[0]=a; o[1]=q;
    }
  }
}

/* ---------------- tf32 conv (attention conv only) ---------------- */
#define XS_TOT 13440
#define XS_BUF 6720
#define WS_BUF 2880

__device__ __forceinline__ void conv_load(float* Xs, float* Ws,
    const float* inb, const float* wb, int tileY, int oc0, int ic0, int p, int tid)
{
  #pragma unroll
  for (int k=0;k<6;k++){
    int t = tid + k*256;
    int ic = t / 192;
    int rem = t - ic*192;
    int r = rem >> 5, gc = rem & 31;
    int gy = tileY + r - 1;
    int ok = ((unsigned)gy < 128u);
    const float* src = inb + ((size_t)(ic0+ic)*Hh + (ok?gy:0))*Wd + gc*4;
    float* dst = Xs + (size_t)(p*8+ic)*840 + r*140 + 4 + gc*4;
    cp16(dst, src, ok);
  }
  #pragma unroll
  for (int k=0;k<3;k++){
    int t = tid + k*256;
    if (t < 576){
      int tap = t / 64;
      int rem = t - tap*64;
      int ic = rem >> 3, gc = rem & 7;
      const float* src = wb + ((size_t)tap*Cc + ic0+ic)*Cc + oc0 + gc*4;
      float* dst = Ws + (size_t)(p*9+tap)*320 + ic*40 + gc*4;
      cp16(dst, src, 1);
    }
  }
}

__global__ void __launch_bounds__(256, 2)
k_conv_mma(const float* __restrict__ in, const float* __restrict__ wt,
           long wstride, float* __restrict__ out, int round_out, int stat_slot)
{
  extern __shared__ float sm_[];
  float* Xs = sm_;
  float* Ws = sm_ + XS_TOT;
  __shared__ float s_red[8][2];
  const int b = blockIdx.z, oc0 = blockIdx.y*32, tileY = blockIdx.x*4;
  const float* inb = in + (size_t)b*NPB;
  const float* wb  = wt + (size_t)b*wstride;
  const int tid = threadIdx.x, wid = tid>>5, lane = tid&31;
  const int g = lane>>2, tig = lane&3;
  const int rowb = wid>>1, x0 = (wid&1)*64;

  for (int t = tid; t < 96; t += 256){ Xs[t*140+3]=0.f; Xs[t*140+132]=0.f; }

  float c[2][8][4];
  #pragma unroll
  for (int m=0;m<2;m++)
    #pragma unroll
    for (int j=0;j<8;j++)
      #pragma unroll
      for (int k=0;k<4;k++) c[m][j][k]=0.f;

  conv_load(Xs, Ws, inb, wb, tileY, oc0, 0, 0, tid);
  asm volatile("cp.async.commit_group;");

  for (int cc = 0; cc < 12; cc++){
    const int p = cc & 1;
    if (cc < 11){
      conv_load(Xs, Ws, inb, wb, tileY, oc0, (cc+1)*8, p^1, tid);
      asm volatile("cp.async.commit_group;");
      asm volatile("cp.async.wait_group 1;");
    } else {
      asm volatile("cp.async.wait_group 0;");
    }
    __syncthreads();

    const float* Xp = Xs + p*XS_BUF;
    const float* Wp = Ws + p*WS_BUF;
    #pragma unroll
    for (int tap = 0; tap < 9; tap++){
      const int dy = tap/3, dx = tap%3;
      const float* w0 = Wp + tap*320;
      unsigned a0[4], a1[4];
      a0[0]=__float_as_uint(w0[ tig   *40 + g   ]);
      a0[1]=__float_as_uint(w0[ tig   *40 + g+8 ]);
      a0[2]=__float_as_uint(w0[(tig+4)*40 + g   ]);
      a0[3]=__float_as_uint(w0[(tig+4)*40 + g+8 ]);
      a1[0]=__float_as_uint(w0[ tig   *40 + g+16]);
      a1[1]=__float_as_uint(w0[ tig   *40 + g+24]);
      a1[2]=__float_as_uint(w0[(tig+4)*40 + g+16]);
      a1[3]=__float_as_uint(w0[(tig+4)*40 + g+24]);
      const float* xr0 = Xp +  tig   *840 + (rowb+dy)*140;
      const float* xr1 = Xp + (tig+4)*840 + (rowb+dy)*140;
      #pragma unroll
      for (int j = 0; j < 8; j++){
        int xb = x0 + 8*j + g + dx + 3;
        unsigned b0 = __float_as_uint(xr0[xb]);
        unsigned b1 = __float_as_uint(xr1[xb]);
        mma_tf32(c[0][j], a0, b0, b1);
        mma_tf32(c[1][j], a1, b0, b1);
      }
    }
    __syncthreads();
  }

  const int y = tileY + rowb;
  float psum=0.f, psq=0.f;
  #pragma unroll
  for (int m=0;m<2;m++){
    #pragma unroll
    for (int j=0;j<8;j++){
      int oc = oc0 + 16*m + g;
      int px = x0 + 8*j + 2*tig;
      size_t o0 = (((size_t)b*Cc + oc  )*Hh + y)*Wd + px;
      size_t o1 = (((size_t)b*Cc + oc+8)*Hh + y)*Wd + px;
      float v00=c[m][j][0], v01=c[m][j][1], v10=c[m][j][2], v11=c[m][j][3];
      if (round_out){
        v00=__uint_as_float(f2tf(v00)); v01=__uint_as_float(f2tf(v01));
        v10=__uint_as_float(f2tf(v10)); v11=__uint_as_float(f2tf(v11));
      }
      psum += (v00+v01)+(v10+v11);
      psq  += v00*v00 + v01*v01 + v10*v10 + v11*v11;
      *(float2*)(out+o0) = make_float2(v00,v01);
      *(float2*)(out+o1) = make_float2(v10,v11);
    }
  }
  if (stat_slot >= 0){
    psum = warp_sum(psum); psq = warp_sum(psq);
    if (lane==0){ s_red[wid][0]=psum; s_red[wid][1]=psq; }
    __syncthreads();
    if (tid==0){
      float a=0.f, q=0.f;
      for (int i=0;i<8;i++){ a+=s_red[i][0]; q+=s_red[i][1]; }
      float* o = &g_part[((stat_slot*8+b)*96 + blockIdx.x*3 + blockIdx.y)*4];
      o[0]=a; o[1]=q;
    }
  }
}

/* ---------------- attention GEMM (4-way L-split) ---------------- */
__global__ void k_attn_gemm(const float* __restrict__ K1, const float* __restrict__ Q1,
                            float* __restrict__ attn)
{
  __shared__ float sk[16][96];
  __shared__ float sq[16][96];
  const int kidx = blockIdx.x;
  const int kh = kidx/3, kw = kidx%3;
  const int b = blockIdx.y;
  const int ls = blockIdx.z;
  const int lbeg = ls*441, lend = lbeg + 441;
  const int tid = threadIdx.x;
  const int q0 = (tid >> 4) * 6;
  const int c0 = (tid & 15) * 6;
  float acc[6][6];
  #pragma unroll
  for (int i=0;i<6;i++)
    #pragma unroll
    for (int j=0;j<6;j++) acc[i][j]=0.f;

  for (int l0 = lbeg; l0 < lend; l0 += 16){
    for (int idx = tid; idx < 1536; idx += 256){
      int c = idx >> 4; int ll = idx & 15;
      int l = l0 + ll;
      float kv=0.f, qv=0.f;
      if (l < lend){
        int ho = l/42, wo = l - ho*42;
        int pix = (3*ho+kh)*Wd + (3*wo+kw);
        size_t off = ((size_t)b*Cc + c)*HW + pix;
        kv = K1[off]; qv = Q1[off];
      }
      sk[ll][c]=kv; sq[ll][c]=qv;
    }
    __syncthreads();
    #pragma unroll
    for (int ll=0; ll<16; ll++){
      float qv[6], cv[6];
      #pragma unroll
      for (int i=0;i<6;i++) qv[i]=sq[ll][q0+i];
      #pragma unroll
      for (int j=0;j<6;j++) cv[j]=sk[ll][c0+j];
      #pragma unroll
      for (int i=0;i<6;i++)
        #pragma unroll
        for (int j=0;j<6;j++) acc[i][j] += qv[i]*cv[j];
    }
    __syncthreads();
  }
  float* op = attn + (size_t)ls*(Bn*Cc*864);
  #pragma unroll
  for (int i=0;i<6;i++)
    #pragma unroll
    for (int j=0;j<6;j++)
      op[((size_t)b*Cc + q0+i)*864 + (size_t)(c0+j)*9 + kidx] = acc[i][j];
}

/* ------- softmax: sum 4 slices, softmax, write tf32 [b][tap][c][q] -------- */
__global__ void k_softmax(float* __restrict__ attn, float* __restrict__ attnT)
{
  __shared__ float sm[8];
  __shared__ float bc;
  const int b = blockIdx.y, q = blockIdx.x, tid = threadIdx.x;
  const size_t SL = (size_t)Bn*Cc*864;
  float* row = attn + ((size_t)(b*Cc+q))*864;
  const float scale = 0.034020690871988586f;
  float mx = -1e30f;
  for (int i=tid;i<864;i+=256){
    float v = (row[i] + row[i+SL] + row[i+2*SL] + row[i+3*SL]) * scale;
    row[i] = v;
    mx = fmaxf(mx, v);
  }
  #pragma unroll
  for (int o=16;o;o>>=1) mx = fmaxf(mx, __shfl_xor_sync(0xffffffffu, mx, o));
  if ((tid&31)==0) sm[tid>>5]=mx;
  __syncthreads();
  if (tid==0){ float v=sm[0]; for(int i=1;i<8;i++) v=fmaxf(v,sm[i]); bc=v; }
  __syncthreads();
  mx = bc;
  float s=0.f;
  for (int i=tid;i<864;i+=256){ float e = expf(row[i] - mx); row[i]=e; s+=e; }
  s = warp_sum(s);
  __syncthreads();
  if ((tid&31)==0) sm[tid>>5]=s;
  __syncthreads();
  if (tid==0){ float v=0.f; for(int i=0;i<8;i++) v+=sm[i]; bc=1.0f/v; }
  __syncthreads();
  float inv = bc;
  for (int i=tid;i<864;i+=256){
    float v = row[i]*inv;
    int cch = i/9, tap = i - 9*cch;
    attnT[(((size_t)b*9 + tap)*Cc + cch)*Cc + q] = __uint_as_float(f2tf(v));
  }
}

/* ----- combine conv-fused partials into g_red slots 2,3 ------ */
__global__ void k_combine23()
{
  int slot = 2 + blockIdx.x;
  int t = threadIdx.x;
  if (t < 16){
    int b = t>>1, c = t&1;
    float s=0.f;
    const float* p = &g_part[((slot*8+b)*96)*4 + c];
    for (int i=0;i<96;i++) s += p[i*4];
    g_red[(slot*8+b)*4 + c] = s;
  }
}

/* ---------------- final epilogue ---------------- */
__global__ void __launch_bounds__(256)
k_final(const float* __restrict__ wf, const float* __restrict__ bias,
        const float* __restrict__ AO, const float* __restrict__ W2,
        const float* __restrict__ A1, const float* __restrict__ XR,
        float* __restrict__ out)
{
  __shared__ float yv[48][128];
  __shared__ float ws[48][96];
  const int b = blockIdx.y;
  const int pix0 = blockIdx.x * 128;
  const int tid = threadIdx.x;
  const int g = tid >> 5;
  const int s = tid & 31;

  float S1 = g_red[(2*8+b)*4+0], SS1 = g_red[(2*8+b)*4+1];
  float m1 = S1*(1.0f/TOTF);
  float inv1 = 1.0f/sqrtf(SS1*(1.0f/TOTF) - m1*m1 + EPSLN);
  float S2 = g_red[(3*8+b)*4+0], SS2 = g_red[(3*8+b)*4+1];
  float m2 = S2*(1.0f/TOTF);
  float inv2 = 1.0f/sqrtf(SS2*(1.0f/TOTF) - m2*m2 + EPSLN);

  float acc[12][4];
  #pragma unroll
  for (int j=0;j<12;j++)
    #pragma unroll
    for (int k=0;k<4;k++) acc[j][k]=0.f;

  for (int i0=0; i0<192; i0+=48){
    for (int idx=tid; idx<48*128; idx+=256){
      int ii = idx >> 7; int p = idx & 127;
      int i = i0+ii;
      float v;
      if (i < 96){
        v = (AO[((size_t)b*Cc+i)*HW + pix0+p]-m1)*inv1;
      } else {
        size_t o = ((size_t)b*Cc+(i-96))*HW + pix0+p;
        v = (W2[o]-m2)*inv2*A1[o];
      }
      yv[ii][p] = v;
    }
    for (int idx=tid; idx<48*96; idx+=256){
      int ii = idx/96, o = idx-ii*96;
      ws[ii][o] = wf[(size_t)o*192 + i0+ii];
    }
    __syncthreads();
    #pragma unroll 4
    for (int ii=0; ii<48; ii++){
      float4 v = *(const float4*)&yv[ii][s*4];
      float4 w0 = *(const float4*)&ws[ii][g*12];
      float4 w1 = *(const float4*)&ws[ii][g*12+4];
      float4 w2 = *(const float4*)&ws[ii][g*12+8];
      float wv[12] = {w0.x,w0.y,w0.z,w0.w, w1.x,w1.y,w1.z,w1.w, w2.x,w2.y,w2.z,w2.w};
      #pragma unroll
      for (int j=0;j<12;j++){
        acc[j][0] += wv[j]*v.x; acc[j][1] += wv[j]*v.y;
        acc[j][2] += wv[j]*v.z; acc[j][3] += wv[j]*v.w;
      }
    }
    __syncthreads();
  }
  #pragma unroll
  for (int j=0;j<12;j++){
    int o = g*12+j;
    size_t off = ((size_t)b*Cc+o)*HW + pix0 + s*4;
    float bb = bias[o];
    float4 xr = *(const float4*)(XR+off);
    float4 ov = make_float4(xr.x+bb+acc[j][0], xr.y+bb+acc[j][1],
                            xr.z+bb+acc[j][2], xr.w+bb+acc[j][3]);
    *(float4*)(out+off) = ov;
  }
}

/* ---------------- host ---------------- */
extern "C" void kernel_launch(void* const* d_in, const int* in_sizes, int n_in,
                              void* d_out, int out_size)
{
  const float* x    = (const float*)d_in[0];
  const float* wc2  = (const float*)d_in[1];
  const float* aw1  = (const float*)d_in[2];
  const float* aw2  = (const float*)d_in[3];
  const float* aw3  = (const float*)d_in[4];
  const float* wf   = (const float*)d_in[5];
  const float* bf   = (const float*)d_in[6];
  const float* sc1  = (const float*)d_in[7];
  const float* sc2  = (const float*)d_in[8];
  const float* rc   = (const float*)d_in[9];
  const float* nc1  = (const float*)d_in[10];
  const float* nc2  = (const float*)d_in[11];

  float *pA1,*pXR,*pK1,*pQ1,*pV,*pW2,*pAO,*pATTN,*pATTNT;
  unsigned *pA1h,*pA2h,*pWTh;
  cudaGetSymbolAddress((void**)&pA1,  g_bA1);
  cudaGetSymbolAddress((void**)&pA1h, g_bA1h);
  cudaGetSymbolAddress((void**)&pA2h, g_bA2h);
  cudaGetSymbolAddress((void**)&pXR,  g_bXR);
  cudaGetSymbolAddress((void**)&pK1,  g_bK1);
  cudaGetSymbolAddress((void**)&pQ1,  g_bQ1);
  cudaGetSymbolAddress((void**)&pV ,  g_bV );
  cudaGetSymbolAddress((void**)&pW2,  g_bW2);
  cudaGetSymbolAddress((void**)&pAO,  g_bAO);
  cudaGetSymbolAddress((void**)&pATTN, g_ATTN);
  cudaGetSymbolAddress((void**)&pATTNT, g_ATTNT);
  cudaGetSymbolAddress((void**)&pWTh, g_WTh);

  static int smem_set = 0;
  if (!smem_set){
    cudaFuncSetAttribute(k_conv_h,   cudaFuncAttributeMaxDynamicSharedMemorySize, CONV_SMEM);
    cudaFuncSetAttribute(k_conv_mma, cudaFuncAttributeMaxDynamicSharedMemorySize, CONV_SMEM);
    smem_set = 1;
  }
  const long WSTRIDE = 9L*Cc*Cc;
  const int  WH = 9*48*96;                  /* half2 weights per conv */
  const int NB_TOT = NBE + (NWTH + 255)/256;

  /* launch order: #4 (first fp16 conv) is what ncu captures */
  k_reduce_ss <<<dim3(64,8),256>>>(x);                                   /* 1 */
  k_reduce_pos<<<dim3(64,8),256>>>(x);                                   /* 2 */
  k_elemwise<<<NB_TOT,256>>>(x, sc1,sc2,rc,nc1,nc2,                      /* 3 */
                             pA1, pA1h, pA2h, pXR, aw1, aw2, aw3, wc2);
  k_conv_h<<<dim3(32,3,8),256,CONV_SMEM>>>(pA1h, pWTh+0*WH, pK1, 0, -1); /* 4: PROFILED */
  k_conv_h<<<dim3(32,3,8),256,CONV_SMEM>>>(pA2h, pWTh+1*WH, pQ1, 0, -1);
  k_conv_h<<<dim3(32,3,8),256,CONV_SMEM>>>(pA1h, pWTh+2*WH, pV , 1, -1);
  k_conv_h<<<dim3(32,3,8),256,CONV_SMEM>>>(pA2h, pWTh+3*WH, pW2, 0,  3);

  k_attn_gemm<<<dim3(9,8,4),256>>>(pK1, pQ1, pATTN);
  k_softmax  <<<dim3(96,8),256>>>(pATTN, pATTNT);

  k_conv_mma<<<dim3(32,3,8),256,CONV_SMEM>>>(pV, pATTNT, WSTRIDE, pAO, 0, 2);

  k_combine23<<<2,32>>>();
  k_final<<<dim3(HW/128,8),256>>>(wf, bf, pAO, pW2, pA1, pXR, (float*)d_out);
}

// round 13
// speedup vs baseline: 5.3303x; 1.1340x over previous
#include <cuda_runtime.h>
#include <cuda_fp16.h>
#include <math.h>

#define Bn 8
#define Cc 96
#define Hh 128
#define Wd 128
#define HW (Hh*Wd)
#define NPB (Cc*HW)
#define NELEM (Bn*NPB)
#define TOTF 1572864.0f
#define EPSLN 1e-5f
#define NBE (NELEM/4/256)          /* elemwise main blocks: 12288 */
#define NWTH (4*9*48*96)           /* packed half2 weight entries */
#define WHB (9*48*96)              /* half2 weights per conv / per batch */

/* ---------------- scratch (device globals; no allocation) ---------------- */
__device__ float4   g_bA1 [NELEM/4];     /* x1 fp32 (k_final)            */
__device__ unsigned g_bA1h[NELEM/2];     /* x1 half2 packed [cp][pix]    */
__device__ unsigned g_bA2h[NELEM/2];     /* x2 half2 packed              */
__device__ float4   g_bXR [NELEM/4];
__device__ float4   g_bK1 [NELEM/4];
__device__ float4   g_bQ1 [NELEM/4];
__device__ unsigned g_bVh [NELEM/2];     /* V half2 packed [cp][pix]     */
__device__ float4   g_bW2 [NELEM/4];
__device__ float4   g_bAO [NELEM/4];
__device__ float    g_ATTN [4*Bn*Cc*864];
__device__ unsigned g_ATTNTh[Bn*WHB];    /* softmaxed half2 [b][tap][icp][q] */
__device__ unsigned g_WTh[NWTH];         /* fixed w half2 [w][tap][icp][oc] */
__device__ float    g_part[4*8*96*4];
__device__ float    g_red [4*8*4];
__device__ float    g_coef[8*8];
__device__ int      g_ctr;

/* ---------------- helpers ---------------- */
__device__ __forceinline__ float warp_sum(float v){
  #pragma unroll
  for (int o=16;o;o>>=1) v += __shfl_xor_sync(0xffffffffu, v, o);
  return v;
}
__device__ __forceinline__ unsigned f2tf(float f){
  unsigned r; asm("cvt.rna.tf32.f32 %0, %1;" : "=r"(r) : "f"(f)); return r;
}
__device__ __forceinline__ unsigned packh2(float lo, float hi){
  __half2 h = __halves2half2(__float2half_rn(lo), __float2half_rn(hi));
  return *(unsigned*)&h;
}
__device__ __forceinline__ void mma_tf32(float c[4], const unsigned a[4],
                                         unsigned b0, unsigned b1){
  asm volatile("mma.sync.aligned.m16n8k8.row.col.f32.tf32.tf32.f32 "
               "{%0,%1,%2,%3},{%4,%5,%6,%7},{%8,%9},{%0,%1,%2,%3};"
               : "+f"(c[0]),"+f"(c[1]),"+f"(c[2]),"+f"(c[3])
               : "r"(a[0]),"r"(a[1]),"r"(a[2]),"r"(a[3]),"r"(b0),"r"(b1));
}
__device__ __forceinline__ void mma_f16(float c[4], const unsigned a[4],
                                        unsigned b0, unsigned b1){
  asm volatile("mma.sync.aligned.m16n8k16.row.col.f32.f16.f16.f32 "
               "{%0,%1,%2,%3},{%4,%5,%6,%7},{%8,%9},{%0,%1,%2,%3};"
               : "+f"(c[0]),"+f"(c[1]),"+f"(c[2]),"+f"(c[3])
               : "r"(a[0]),"r"(a[1]),"r"(a[2]),"r"(a[3]),"r"(b0),"r"(b1));
}
__device__ __forceinline__ void cp16(void* dst, const void* src, int ok){
  unsigned d = (unsigned)__cvta_generic_to_shared(dst);
  asm volatile("cp.async.ca.shared.global [%0], [%1], 16, %2;"
               :: "r"(d), "l"(src), "r"(ok?16:0));
}

/* ---------------- stage 1: sum/sumsq of x ---------------- */
__global__ void k_reduce_ss(const float* __restrict__ in)
{
  __shared__ float sm[2][8];
  int b = blockIdx.y;
  if (blockIdx.x==0 && b==0 && threadIdx.x==0) g_ctr = 0;
  const float4* p = (const float4*)in + (size_t)b*(NPB/4);
  float s=0.f, ss=0.f;
  for (int i = blockIdx.x*blockDim.x + threadIdx.x; i < NPB/4; i += gridDim.x*blockDim.x){
    float4 v = p[i];
    s  += (v.x+v.y)+(v.z+v.w);
    ss += v.x*v.x + v.y*v.y + v.z*v.z + v.w*v.w;
  }
  s = warp_sum(s); ss = warp_sum(ss);
  int lane = threadIdx.x&31, w = threadIdx.x>>5;
  if (lane==0){ sm[0][w]=s; sm[1][w]=ss; }
  __syncthreads();
  if (threadIdx.x==0){
    float a=0.f,c=0.f;
    for (int i=0;i<8;i++){ a+=sm[0][i]; c+=sm[1][i]; }
    float* o = &g_part[((0*8+b)*96 + blockIdx.x)*4];
    o[0]=a; o[1]=c;
  }
}

/* ---------------- stage 2: pos-stats; last block emits coefficients ------ */
__global__ void k_reduce_pos(const float* __restrict__ in)
{
  __shared__ float sm[3][8];
  __shared__ float s_mu;
  __shared__ int   s_last;
  int b = blockIdx.y;
  int tid = threadIdx.x;
  if (tid==0){
    float S=0.f;
    const float* pp = &g_part[((0*8+b)*96)*4];
    for (int i=0;i<64;i++) S += pp[i*4];
    s_mu = S*(1.0f/TOTF);
  }
  __syncthreads();
  float m = s_mu;
  const float4* p = (const float4*)in + (size_t)b*(NPB/4);
  float P=0.f, PP=0.f, cnt=0.f;
  for (int i = blockIdx.x*blockDim.x + tid; i < NPB/4; i += gridDim.x*blockDim.x){
    float4 v = p[i];
    float a;
    a=v.x-m; if(a>0.f){P+=a;PP+=a*a;cnt+=1.f;}
    a=v.y-m; if(a>0.f){P+=a;PP+=a*a;cnt+=1.f;}
    a=v.z-m; if(a>0.f){P+=a;PP+=a*a;cnt+=1.f;}
    a=v.w-m; if(a>0.f){P+=a;PP+=a*a;cnt+=1.f;}
  }
  P = warp_sum(P); PP = warp_sum(PP); cnt = warp_sum(cnt);
  int lane = tid&31, w = tid>>5;
  if (lane==0){ sm[0][w]=P; sm[1][w]=PP; sm[2][w]=cnt; }
  __syncthreads();
  if (tid==0){
    float a=0.f,c=0.f,d=0.f;
    for (int i=0;i<8;i++){ a+=sm[0][i]; c+=sm[1][i]; d+=sm[2][i]; }
    float* o = &g_part[((1*8+b)*96 + blockIdx.x)*4];
    o[0]=a; o[1]=c; o[2]=d;
    __threadfence();
    int old = atomicAdd(&g_ctr, 1);
    s_last = (old == (int)(gridDim.x*gridDim.y) - 1);
  }
  __syncthreads();
  if (s_last && tid < 8){
    int bb = tid;
    volatile float* vp = g_part;
    float S=0.f, SS=0.f, Ps=0.f, PPs=0.f, np=0.f;
    for (int i=0;i<64;i++){
      S  += vp[((0*8+bb)*96+i)*4+0];
      SS += vp[((0*8+bb)*96+i)*4+1];
      Ps += vp[((1*8+bb)*96+i)*4+0];
      PPs+= vp[((1*8+bb)*96+i)*4+1];
      np += vp[((1*8+bb)*96+i)*4+2];
    }
    float T = TOTF;
    float mm = S/T;
    float neg = T - np;
    float avg1 = Ps/np;
    float mean1 = (Ps + avg1*neg)/T;
    float var1  = (PPs + avg1*avg1*neg)/T - mean1*mean1;
    float inv1  = 1.0f/sqrtf(var1 + EPSLN);
    float s1    = sqrtf(np/T);
    float SSc = SS - S*S/T;
    float QQ  = SSc - PPs;
    float avg2  = -Ps/neg;
    float mean2 = (-Ps + avg2*np)/T;
    float var2  = (QQ + avg2*avg2*np)/T - mean2*mean2;
    float inv2  = 1.0f/sqrtf(var2 + EPSLN);
    float s2    = sqrtf(neg/T);
    float* c = &g_coef[bb*8];
    c[0]=mm; c[1]=mean1; c[2]=s1*inv1; c[3]=s1*(avg1-mean1)*inv1;
    c[4]=mean2; c[5]=s2*inv2; c[6]=s2*(avg2-mean2)*inv2;
  }
}

/* ------ elementwise: A1(f32), A1h/A2h (packed half2), XR; + weight tail -- */
__global__ void k_elemwise(const float* __restrict__ x,
    const float* __restrict__ sc1p, const float* __restrict__ sc2p,
    const float* __restrict__ rcp,  const float* __restrict__ nc1p,
    const float* __restrict__ nc2p,
    float* __restrict__ A1, unsigned* __restrict__ A1h,
    unsigned* __restrict__ A2h, float* __restrict__ XR,
    const float* __restrict__ w0, const float* __restrict__ w1,
    const float* __restrict__ w2, const float* __restrict__ w3)
{
  if (blockIdx.x >= NBE){
    int idx = (blockIdx.x - NBE)*256 + threadIdx.x;
    if (idx < NWTH){
      int w   = idx / WHB;
      int rem = idx - w*WHB;
      int tap = rem / (48*96);
      int rem2= rem - tap*(48*96);
      int icp = rem2 / 96;
      int oc  = rem2 - icp*96;
      const float* src = (w==0)?w0:(w==1)?w1:(w==2)?w2:w3;
      float vlo = src[((size_t)oc*Cc + 2*icp  )*9 + tap];
      float vhi = src[((size_t)oc*Cc + 2*icp+1)*9 + tap];
      g_WTh[idx] = packh2(vlo, vhi);
    }
    return;
  }
  int gidx = blockIdx.x*256 + threadIdx.x;
  int p2   = gidx & 8191;            /* HW/2 */
  int rest = gidx >> 13;
  int cp   = rest % 48;
  int b    = rest / 48;
  const float* cf = &g_coef[b*8];
  float m=cf[0], mean1=cf[1], g1=cf[2], c1n=cf[3], mean2=cf[4], g2=cf[5], c2n=cf[6];
  float sc1=sc1p[0], sc2=sc2p[0], rc=rcp[0], nc1=nc1p[0], nc2=nc2p[0];
  size_t base0 = ((size_t)b*Cc + 2*cp)*HW + 2*p2;
  float2 xa = *(const float2*)(x + base0);
  float2 xb = *(const float2*)(x + base0 + HW);
  float xi[2][2] = {{xa.x, xa.y},{xb.x, xb.y}};
  float o1[2][2], o2[2][2], o3[2][2];
  #pragma unroll
  for (int cI=0;cI<2;cI++){
    #pragma unroll
    for (int pI=0;pI<2;pI++){
      float xc = xi[cI][pI]-m;
      float x1n, x2n, v1, v2;
      if (xc > 0.f){ x1n=(xc-mean1)*g1; x2n=c2n; v1=sc1*xc+x1n; v2=x2n; }
      else         { x1n=c1n; x2n=(xc-mean2)*g2; v1=x1n; v2=sc2*xc+x2n; }
      o1[cI][pI]=v1; o2[cI][pI]=v2; o3[cI][pI]=0.5f*(nc1*x1n+nc2*x2n)+rc*xc;
    }
  }
  *(float2*)(A1+base0)      = make_float2(o1[0][0],o1[0][1]);
  *(float2*)(A1+base0+HW)   = make_float2(o1[1][0],o1[1][1]);
  *(float2*)(XR+base0)      = make_float2(o3[0][0],o3[0][1]);
  *(float2*)(XR+base0+HW)   = make_float2(o3[1][0],o3[1][1]);
  size_t ho = (size_t)b*(NPB/2) + (size_t)cp*HW + 2*p2;
  *(uint2*)(A1h+ho) = make_uint2(packh2(o1[0][0],o1[1][0]), packh2(o1[0][1],o1[1][1]));
  *(uint2*)(A2h+ho) = make_uint2(packh2(o2[0][0],o2[1][0]), packh2(o2[0][1],o2[1][1]));
}

/* ---------------- fp16 conv: m16n8k16, cp.async double-buffered -----------
   block: 4 y-rows x 128 px x 32 oc. mode 0 = fp32 out; 1 = half2-packed.   */
#define HX_BUF 6720
#define HW_BUF 2880
#define CONV_SMEM ((2*HX_BUF + 2*HW_BUF)*4)   /* 76800 B */

__device__ __forceinline__ void conv_load_h(unsigned* Xs, unsigned* Ws,
    const unsigned* inb, const unsigned* wbh, int tileY, int oc0, int cc, int p, int tid)
{
  #pragma unroll
  for (int k=0;k<6;k++){
    int t = tid + k*256;
    int icp = t / 192;
    int rem = t - icp*192;
    int r = rem >> 5, gc = rem & 31;
    int gy = tileY + r - 1;
    int ok = ((unsigned)gy < 128u);
    const unsigned* src = inb + (size_t)(cc*8+icp)*HW + (ok?gy:0)*Wd + gc*4;
    unsigned* dst = Xs + (size_t)(p*8+icp)*840 + r*140 + 4 + gc*4;
    cp16(dst, src, ok);
  }
  #pragma unroll
  for (int k=0;k<3;k++){
    int t = tid + k*256;
    if (t < 576){
      int tap = t / 64;
      int rem = t - tap*64;
      int icp = rem >> 3, gc = rem & 7;
      const unsigned* src = wbh + ((size_t)tap*48 + cc*8+icp)*96 + oc0 + gc*4;
      unsigned* dst = Ws + ((size_t)(p*9+tap)*8 + icp)*40 + gc*4;
      cp16(dst, src, 1);
    }
  }
}

__global__ void __launch_bounds__(256, 2)
k_conv_h(const unsigned* __restrict__ in, const unsigned* __restrict__ wbh0,
         long wstride, float* __restrict__ out, unsigned* __restrict__ outh,
         int mode, int stat_slot)
{
  extern __shared__ unsigned smh_[];
  unsigned* Xs = smh_;
  unsigned* Ws = smh_ + 2*HX_BUF;
  __shared__ float s_red[8][2];
  const int b = blockIdx.z, oc0 = blockIdx.y*32, tileY = blockIdx.x*4;
  const unsigned* inb = in + (size_t)b*(NPB/2);
  const unsigned* wbh = wbh0 + (size_t)b*wstride;
  const int tid = threadIdx.x, wid = tid>>5, lane = tid&31;
  const int g = lane>>2, tig = lane&3;
  const int rowb = wid>>1, x0 = (wid&1)*64;

  for (int t = tid; t < 96; t += 256){ Xs[t*140+3]=0u; Xs[t*140+132]=0u; }

  float c[2][8][4];
  #pragma unroll
  for (int m=0;m<2;m++)
    #pragma unroll
    for (int j=0;j<8;j++)
      #pragma unroll
      for (int k=0;k<4;k++) c[m][j][k]=0.f;

  conv_load_h(Xs, Ws, inb, wbh, tileY, oc0, 0, 0, tid);
  asm volatile("cp.async.commit_group;");

  for (int cc = 0; cc < 6; cc++){
    const int p = cc & 1;
    if (cc < 5){
      conv_load_h(Xs, Ws, inb, wbh, tileY, oc0, cc+1, p^1, tid);
      asm volatile("cp.async.commit_group;");
      asm volatile("cp.async.wait_group 1;");
    } else {
      asm volatile("cp.async.wait_group 0;");
    }
    __syncthreads();

    const unsigned* Xp = Xs + p*HX_BUF;
    const unsigned* Wp = Ws + p*HW_BUF;
    #pragma unroll
    for (int tap = 0; tap < 9; tap++){
      const int dy = tap/3, dx = tap%3;
      const unsigned* w0 = Wp + tap*320;
      unsigned a0[4], a1[4];
      a0[0]=w0[ tig   *40 + g   ];
      a0[1]=w0[ tig   *40 + g+8 ];
      a0[2]=w0[(tig+4)*40 + g   ];
      a0[3]=w0[(tig+4)*40 + g+8 ];
      a1[0]=w0[ tig   *40 + g+16];
      a1[1]=w0[ tig   *40 + g+24];
      a1[2]=w0[(tig+4)*40 + g+16];
      a1[3]=w0[(tig+4)*40 + g+24];
      const unsigned* xr0 = Xp +  tig   *840 + (rowb+dy)*140;
      const unsigned* xr1 = Xp + (tig+4)*840 + (rowb+dy)*140;
      #pragma unroll
      for (int j = 0; j < 8; j++){
        int xb = x0 + 8*j + g + dx + 3;
        unsigned b0 = xr0[xb];
        unsigned b1 = xr1[xb];
        mma_f16(c[0][j], a0, b0, b1);
        mma_f16(c[1][j], a1, b0, b1);
      }
    }
    __syncthreads();
  }

  const int y = tileY + rowb;
  if (mode == 0){
    float psum=0.f, psq=0.f;
    #pragma unroll
    for (int m=0;m<2;m++){
      #pragma unroll
      for (int j=0;j<8;j++){
        int oc = oc0 + 16*m + g;
        int px = x0 + 8*j + 2*tig;
        size_t o0 = (((size_t)b*Cc + oc  )*Hh + y)*Wd + px;
        size_t o1 = (((size_t)b*Cc + oc+8)*Hh + y)*Wd + px;
        float v00=c[m][j][0], v01=c[m][j][1], v10=c[m][j][2], v11=c[m][j][3];
        psum += (v00+v01)+(v10+v11);
        psq  += v00*v00 + v01*v01 + v10*v10 + v11*v11;
        *(float2*)(out+o0) = make_float2(v00,v01);
        *(float2*)(out+o1) = make_float2(v10,v11);
      }
    }
    if (stat_slot >= 0){
      psum = warp_sum(psum); psq = warp_sum(psq);
      if (lane==0){ s_red[wid][0]=psum; s_red[wid][1]=psq; }
      __syncthreads();
      if (tid==0){
        float a=0.f, q=0.f;
        for (int i=0;i<8;i++){ a+=s_red[i][0]; q+=s_red[i][1]; }
        float* o = &g_part[((stat_slot*8+b)*96 + blockIdx.x*3 + blockIdx.y)*4];
        o[0]=a; o[1]=q;
      }
    }
  } else {
    /* half2-packed output: lane pair g <-> g+1 via shfl_xor 4 (lane bit2) */
    size_t base = (size_t)b*(NPB/2);
    #pragma unroll
    for (int m=0;m<2;m++){
      #pragma unroll
      for (int j=0;j<8;j++){
        float v00=c[m][j][0], v01=c[m][j][1], v10=c[m][j][2], v11=c[m][j][3];
        float p00 = __shfl_xor_sync(0xffffffffu, v00, 4);
        float p01 = __shfl_xor_sync(0xffffffffu, v01, 4);
        float p10 = __shfl_xor_sync(0xffffffffu, v10, 4);
        float p11 = __shfl_xor_sync(0xffffffffu, v11, 4);
        if ((g & 1) == 0){
          int oc  = oc0 + 16*m + g;
          int px  = x0 + 8*j + 2*tig;
          size_t o0 = base + (size_t)(oc>>1)    *HW + (size_t)y*Wd + px;
          size_t o1 = base + (size_t)((oc+8)>>1)*HW + (size_t)y*Wd + px;
          *(uint2*)(outh+o0) = make_uint2(packh2(v00,p00), packh2(v01,p01));
          *(uint2*)(outh+o1) = make_uint2(packh2(v10,p10), packh2(v11,p11));
        }
      }
    }
  }
}

/* ---------------- attention GEMM (4-way L-split) ---------------- */
__global__ void k_attn_gemm(const float* __restrict__ K1, const float* __restrict__ Q1,
                            float* __restrict__ attn)
{
  __shared__ float sk[16][96];
  __shared__ float sq[16][96];
  const int kidx = blockIdx.x;
  const int kh = kidx/3, kw = kidx%3;
  const int b = blockIdx.y;
  const int ls = blockIdx.z;
  const int lbeg = ls*441, lend = lbeg + 441;
  const int tid = threadIdx.x;
  const int q0 = (tid >> 4) * 6;
  const int c0 = (tid & 15) * 6;
  float acc[6][6];
  #pragma unroll
  for (int i=0;i<6;i++)
    #pragma unroll
    for (int j=0;j<6;j++) acc[i][j]=0.f;

  for (int l0 = lbeg; l0 < lend; l0 += 16){
    for (int idx = tid; idx < 1536; idx += 256){
      int c = idx >> 4; int ll = idx & 15;
      int l = l0 + ll;
      float kv=0.f, qv=0.f;
      if (l < lend){
        int ho = l/42, wo = l - ho*42;
        int pix = (3*ho+kh)*Wd + (3*wo+kw);
        size_t off = ((size_t)b*Cc + c)*HW + pix;
        kv = K1[off]; qv = Q1[off];
      }
      sk[ll][c]=kv; sq[ll][c]=qv;
    }
    __syncthreads();
    #pragma unroll
    for (int ll=0; ll<16; ll++){
      float qv[6], cv[6];
      #pragma unroll
      for (int i=0;i<6;i++) qv[i]=sq[ll][q0+i];
      #pragma unroll
      for (int j=0;j<6;j++) cv[j]=sk[ll][c0+j];
      #pragma unroll
      for (int i=0;i<6;i++)
        #pragma unroll
        for (int j=0;j<6;j++) acc[i][j] += qv[i]*cv[j];
    }
    __syncthreads();
  }
  float* op = attn + (size_t)ls*(Bn*Cc*864);
  #pragma unroll
  for (int i=0;i<6;i++)
    #pragma unroll
    for (int j=0;j<6;j++)
      op[((size_t)b*Cc + q0+i)*864 + (size_t)(c0+j)*9 + kidx] = acc[i][j];
}

/* --- softmax: sum 4 slices, softmax, write half2 weights [b][tap][icp][q] - */
__global__ void k_softmax(float* __restrict__ attn, unsigned* __restrict__ attnTh)
{
  __shared__ float sm[8];
  __shared__ float bc;
  const int b = blockIdx.y, q = blockIdx.x, tid = threadIdx.x;
  const size_t SL = (size_t)Bn*Cc*864;
  float* row = attn + ((size_t)(b*Cc+q))*864;
  const float scale = 0.034020690871988586f;
  float mx = -1e30f;
  for (int i=tid;i<864;i+=256){
    float v = (row[i] + row[i+SL] + row[i+2*SL] + row[i+3*SL]) * scale;
    row[i] = v;
    mx = fmaxf(mx, v);
  }
  #pragma unroll
  for (int o=16;o;o>>=1) mx = fmaxf(mx, __shfl_xor_sync(0xffffffffu, mx, o));
  if ((tid&31)==0) sm[tid>>5]=mx;
  __syncthreads();
  if (tid==0){ float v=sm[0]; for(int i=1;i<8;i++) v=fmaxf(v,sm[i]); bc=v; }
  __syncthreads();
  mx = bc;
  float s=0.f;
  for (int i=tid;i<864;i+=256){ float e = expf(row[i] - mx); row[i]=e; s+=e; }
  s = warp_sum(s);
  __syncthreads();
  if ((tid&31)==0) sm[tid>>5]=s;
  __syncthreads();
  if (tid==0){ float v=0.f; for(int i=0;i<8;i++) v+=sm[i]; bc=1.0f/v; }
  __syncthreads();
  float inv = bc;
  for (int i2=tid; i2<432; i2+=256){
    int icp = i2/9, tap = i2 - 9*icp;
    float vlo = row[(2*icp  )*9 + tap]*inv;
    float vhi = row[(2*icp+1)*9 + tap]*inv;
    attnTh[(((size_t)b*9 + tap)*48 + icp)*96 + q] = packh2(vlo, vhi);
  }
}

/* ----- combine conv-fused partials into g_red slots 2,3 ------ */
__global__ void k_combine23()
{
  int slot = 2 + blockIdx.x;
  int t = threadIdx.x;
  if (t < 16){
    int b = t>>1, c = t&1;
    float s=0.f;
    const float* p = &g_part[((slot*8+b)*96)*4 + c];
    for (int i=0;i<96;i++) s += p[i*4];
    g_red[(slot*8+b)*4 + c] = s;
  }
}

/* ------- final epilogue: LN + 1x1 conv on tf32 MMA, +XR +bias -------------
   block: 96 oc x 128 px. 8 warps = 2(oc:48) x 4(px:32). K=192 in 4x48.     */
__global__ void __launch_bounds__(256)
k_final(const float* __restrict__ wf, const float* __restrict__ bias,
        const float* __restrict__ AO, const float* __restrict__ W2,
        const float* __restrict__ A1, const float* __restrict__ XR,
        float* __restrict__ out)
{
  __shared__ unsigned yv[48*132];
  __shared__ unsigned ws[48*104];
  const int b = blockIdx.y;
  const int pix0 = blockIdx.x * 128;
  const int tid = threadIdx.x, wid = tid>>5, lane = tid&31;
  const int g = lane>>2, tig = lane&3;
  const int warpM = wid>>2, warpN = wid&3;
  const int oc0 = warpM*48, px0 = warpN*32;

  float S1 = g_red[(2*8+b)*4+0], SS1 = g_red[(2*8+b)*4+1];
  float m1 = S1*(1.0f/TOTF);
  float inv1 = 1.0f/sqrtf(SS1*(1.0f/TOTF) - m1*m1 + EPSLN);
  float S2 = g_red[(3*8+b)*4+0], SS2 = g_red[(3*8+b)*4+1];
  float m2 = S2*(1.0f/TOTF);
  float inv2 = 1.0f/sqrtf(SS2*(1.0f/TOTF) - m2*m2 + EPSLN);

  float c[3][4][4];
  #pragma unroll
  for (int m=0;m<3;m++)
    #pragma unroll
    for (int j=0;j<4;j++)
      #pragma unroll
      for (int k=0;k<4;k++) c[m][j][k]=0.f;

  for (int i0=0; i0<192; i0+=48){
    for (int idx=tid; idx<48*128; idx+=256){
      int ii = idx >> 7; int p = idx & 127;
      int i = i0+ii;
      float v;
      if (i < 96){
        v = (AO[((size_t)b*Cc+i)*HW + pix0+p]-m1)*inv1;
      } else {
        size_t o = ((size_t)b*Cc+(i-96))*HW + pix0+p;
        v = (W2[o]-m2)*inv2*A1[o];
      }
      yv[ii*132+p] = f2tf(v);
    }
    for (int idx=tid; idx<48*96; idx+=256){
      int ii = idx/96, o = idx-ii*96;
      ws[ii*104+o] = f2tf(wf[(size_t)o*192 + i0+ii]);
    }
    __syncthreads();
    #pragma unroll
    for (int ks=0; ks<6; ks++){
      const unsigned* w0 = &ws[(ks*8+tig  )*104];
      const unsigned* w1 = &ws[(ks*8+tig+4)*104];
      unsigned a[3][4];
      #pragma unroll
      for (int m=0;m<3;m++){
        int ocb = oc0 + 16*m + g;
        a[m][0]=w0[ocb]; a[m][1]=w0[ocb+8];
        a[m][2]=w1[ocb]; a[m][3]=w1[ocb+8];
      }
      const unsigned* y0 = &yv[(ks*8+tig  )*132];
      const unsigned* y1 = &yv[(ks*8+tig+4)*132];
      #pragma unroll
      for (int j=0;j<4;j++){
        int xb = px0 + 8*j + g;
        unsigned b0 = y0[xb];
        unsigned b1 = y1[xb];
        #pragma unroll
        for (int m=0;m<3;m++) mma_tf32(c[m][j], a[m], b0, b1);
      }
    }
    __syncthreads();
  }

  #pragma unroll
  for (int m=0;m<3;m++){
    #pragma unroll
    for (int j=0;j<4;j++){
      int oc = oc0 + 16*m + g;
      int px = px0 + 8*j + 2*tig;
      size_t o0 = ((size_t)b*Cc + oc  )*HW + pix0 + px;
      size_t o1 = ((size_t)b*Cc + oc+8)*HW + pix0 + px;
      float b0 = bias[oc], b1 = bias[oc+8];
      float2 x0v = *(const float2*)(XR+o0);
      float2 x1v = *(const float2*)(XR+o1);
      *(float2*)(out+o0) = make_float2(x0v.x+b0+c[m][j][0], x0v.y+b0+c[m][j][1]);
      *(float2*)(out+o1) = make_float2(x1v.x+b1+c[m][j][2], x1v.y+b1+c[m][j][3]);
    }
  }
}

/* ---------------- host ---------------- */
extern "C" void kernel_launch(void* const* d_in, const int* in_sizes, int n_in,
                              void* d_out, int out_size)
{
  const float* x    = (const float*)d_in[0];
  const float* wc2  = (const float*)d_in[1];
  const float* aw1  = (const float*)d_in[2];
  const float* aw2  = (const float*)d_in[3];
  const float* aw3  = (const float*)d_in[4];
  const float* wf   = (const float*)d_in[5];
  const float* bf   = (const float*)d_in[6];
  const float* sc1  = (const float*)d_in[7];
  const float* sc2  = (const float*)d_in[8];
  const float* rc   = (const float*)d_in[9];
  const float* nc1  = (const float*)d_in[10];
  const float* nc2  = (const float*)d_in[11];

  float *pA1,*pXR,*pK1,*pQ1,*pW2,*pAO,*pATTN;
  unsigned *pA1h,*pA2h,*pVh,*pWTh,*pATTNTh;
  cudaGetSymbolAddress((void**)&pA1,  g_bA1);
  cudaGetSymbolAddress((void**)&pA1h, g_bA1h);
  cudaGetSymbolAddress((void**)&pA2h, g_bA2h);
  cudaGetSymbolAddress((void**)&pXR,  g_bXR);
  cudaGetSymbolAddress((void**)&pK1,  g_bK1);
  cudaGetSymbolAddress((void**)&pQ1,  g_bQ1);
  cudaGetSymbolAddress((void**)&pVh,  g_bVh);
  cudaGetSymbolAddress((void**)&pW2,  g_bW2);
  cudaGetSymbolAddress((void**)&pAO,  g_bAO);
  cudaGetSymbolAddress((void**)&pATTN, g_ATTN);
  cudaGetSymbolAddress((void**)&pATTNTh, g_ATTNTh);
  cudaGetSymbolAddress((void**)&pWTh, g_WTh);

  static int smem_set = 0;
  if (!smem_set){
    cudaFuncSetAttribute(k_conv_h, cudaFuncAttributeMaxDynamicSharedMemorySize, CONV_SMEM);
    smem_set = 1;
  }
  const int NB_TOT = NBE + (NWTH + 255)/256;

  /* launch order: #4 (first fp16 conv) is what ncu captures */
  k_reduce_ss <<<dim3(64,8),256>>>(x);                                   /* 1 */
  k_reduce_pos<<<dim3(64,8),256>>>(x);                                   /* 2 */
  k_elemwise<<<NB_TOT,256>>>(x, sc1,sc2,rc,nc1,nc2,                      /* 3 */
                             pA1, pA1h, pA2h, pXR, aw1, aw2, aw3, wc2);
  k_conv_h<<<dim3(32,3,8),256,CONV_SMEM>>>(pA1h, pWTh+0*WHB, 0, pK1, 0, 0, -1); /* 4 */
  k_conv_h<<<dim3(32,3,8),256,CONV_SMEM>>>(pA2h, pWTh+1*WHB, 0, pQ1, 0, 0, -1);
  k_conv_h<<<dim3(32,3,8),256,CONV_SMEM>>>(pA1h, pWTh+2*WHB, 0, 0, pVh, 1, -1);
  k_conv_h<<<dim3(32,3,8),256,CONV_SMEM>>>(pA2h, pWTh+3*WHB, 0, pW2, 0, 0,  3);

  k_attn_gemm<<<dim3(9,8,4),256>>>(pK1, pQ1, pATTN);
  k_softmax  <<<dim3(96,8),256>>>(pATTN, pATTNTh);

  /* per-example attention conv: fp16 path, per-batch weights */
  k_conv_h<<<dim3(32,3,8),256,CONV_SMEM>>>(pVh, pATTNTh, WHB, pAO, 0, 0, 2);

  k_combine23<<<2,32>>>();
  k_final<<<dim3(HW/128,8),256>>>(wf, bf, pAO, pW2, pA1, pXR, (float*)d_out);
}